// round 2
// baseline (speedup 1.0000x reference)
#include <cuda_runtime.h>
#include <math.h>

#define BATCH 8
#define CC 512
#define NN 4096
#define GG 32
#define CPG 16

// ---- scratch (static device globals; allowed by harness rules) ----
__device__ float g_q[(size_t)BATCH * CC * NN];      // 64 MB
__device__ float g_k[(size_t)BATCH * CC * NN];      // 64 MB
__device__ float g_att[(size_t)BATCH * CC * NN];    // 64 MB
__device__ float g_s[(size_t)BATCH * NN * NN];      // 512 MB (scores / probs in place)
__device__ float g_stats[BATCH * GG * 2];           // mean, rstd per (b, g)

// ============================================================
// Kernel 1: GroupNorm statistics. One block per (b, g).
// Group g = channels [g*16, g*16+16), each channel 4096 contiguous floats,
// and consecutive channels are contiguous -> one flat 65536-float range.
// ============================================================
__global__ void gn_stats_kernel(const float* __restrict__ x) {
    int b = blockIdx.x, g = blockIdx.y;
    const float* xp = x + ((size_t)(b * CC) + g * CPG) * NN;
    float s = 0.f, s2 = 0.f;
    for (int i = threadIdx.x; i < CPG * NN; i += 256) {
        float v = xp[i];
        s += v;
        s2 += v * v;
    }
    __shared__ float sh[256], sh2[256];
    sh[threadIdx.x] = s;
    sh2[threadIdx.x] = s2;
    __syncthreads();
    for (int off = 128; off > 0; off >>= 1) {
        if (threadIdx.x < off) {
            sh[threadIdx.x] += sh[threadIdx.x + off];
            sh2[threadIdx.x] += sh2[threadIdx.x + off];
        }
        __syncthreads();
    }
    if (threadIdx.x == 0) {
        const float inv = 1.f / (float)(CPG * NN);
        float mu = sh[0] * inv;
        float var = sh2[0] * inv - mu * mu;
        g_stats[(b * GG + g) * 2 + 0] = mu;
        g_stats[(b * GG + g) * 2 + 1] = rsqrtf(var + 1e-6f);
    }
}

// ============================================================
// Kernel 2: q / k projection GEMM with GroupNorm fused on the input side.
//   out[b][o][n] = bias[o] + sum_c w[o][c] * norm(x[b][c][n])
// blockIdx.z = b*2 + which (0 = q, 1 = k). 64x64 output tile, 256 threads,
// 4x4 microtile, K-chunk of 16.
// ============================================================
__global__ void qk_gemm_kernel(const float* __restrict__ x,
                               const float* __restrict__ qw, const float* __restrict__ qb,
                               const float* __restrict__ kw, const float* __restrict__ kb,
                               const float* __restrict__ gamma, const float* __restrict__ beta) {
    int b = blockIdx.z >> 1;
    int which = blockIdx.z & 1;
    const float* w = which ? kw : qw;
    const float* bias = which ? kb : qb;
    float* out = which ? g_k : g_q;

    int n0 = blockIdx.x * 64;
    int o0 = blockIdx.y * 64;

    __shared__ float Ws[16][68];  // [kk][o]
    __shared__ float Rs[16][68];  // [kk][n]

    int tid = threadIdx.x;
    int tx = tid & 15, ty = tid >> 4;
    float acc[4][4] = {};

    const float* xb = x + (size_t)b * CC * NN;

    for (int c0 = 0; c0 < CC; c0 += 16) {
        // load weights, transposed to [kk][o]
        {
            int kk = tid & 15, ob = tid >> 4;
#pragma unroll
            for (int r = 0; r < 4; r++) {
                int o = o0 + ob + r * 16;
                Ws[kk][ob + r * 16] = w[(size_t)o * CC + c0 + kk];
            }
        }
        // load x tile and normalize on the fly -> [kk][n]
        {
            int nj = tid & 63, kbase = tid >> 6;
#pragma unroll
            for (int r = 0; r < 4; r++) {
                int kk = kbase + r * 4;
                int c = c0 + kk;
                int g = c >> 4;
                float mu = g_stats[(b * GG + g) * 2 + 0];
                float rstd = g_stats[(b * GG + g) * 2 + 1];
                float v = xb[(size_t)c * NN + n0 + nj];
                Rs[kk][nj] = (v - mu) * rstd * gamma[c] + beta[c];
            }
        }
        __syncthreads();
#pragma unroll
        for (int kk = 0; kk < 16; kk++) {
            float4 a4 = *reinterpret_cast<const float4*>(&Ws[kk][ty * 4]);
            float4 b4 = *reinterpret_cast<const float4*>(&Rs[kk][tx * 4]);
            float a[4] = {a4.x, a4.y, a4.z, a4.w};
            float bb[4] = {b4.x, b4.y, b4.z, b4.w};
#pragma unroll
            for (int i = 0; i < 4; i++)
#pragma unroll
                for (int j = 0; j < 4; j++) acc[i][j] += a[i] * bb[j];
        }
        __syncthreads();
    }

#pragma unroll
    for (int i = 0; i < 4; i++) {
        int o = o0 + ty * 4 + i;
        float bv = bias[o];
        float* op = out + ((size_t)b * CC + o) * NN + n0 + tx * 4;
        float4 v = make_float4(acc[i][0] + bv, acc[i][1] + bv, acc[i][2] + bv, acc[i][3] + bv);
        *reinterpret_cast<float4*>(op) = v;
    }
}

// ============================================================
// Kernel 3: scores GEMM. S[b][n][m] = scale * sum_c q[b][c][n] * k[b][c][m]
// Both operands are read along their contiguous (n / m) dimension.
// ============================================================
__global__ void scores_gemm_kernel() {
    int b = blockIdx.z;
    int m0 = blockIdx.x * 64;
    int n0 = blockIdx.y * 64;

    __shared__ float Qs[16][68];  // [kk][n]
    __shared__ float Ks[16][68];  // [kk][m]

    int tid = threadIdx.x;
    int tx = tid & 15, ty = tid >> 4;
    float acc[4][4] = {};

    const float* qp = g_q + (size_t)b * CC * NN;
    const float* kp = g_k + (size_t)b * CC * NN;

    for (int c0 = 0; c0 < CC; c0 += 16) {
        int col = tid & 63, kbase = tid >> 6;
#pragma unroll
        for (int r = 0; r < 4; r++) {
            int kk = kbase + r * 4;
            Qs[kk][col] = qp[(size_t)(c0 + kk) * NN + n0 + col];
            Ks[kk][col] = kp[(size_t)(c0 + kk) * NN + m0 + col];
        }
        __syncthreads();
#pragma unroll
        for (int kk = 0; kk < 16; kk++) {
            float4 a4 = *reinterpret_cast<const float4*>(&Qs[kk][ty * 4]);
            float4 b4 = *reinterpret_cast<const float4*>(&Ks[kk][tx * 4]);
            float a[4] = {a4.x, a4.y, a4.z, a4.w};
            float bb[4] = {b4.x, b4.y, b4.z, b4.w};
#pragma unroll
            for (int i = 0; i < 4; i++)
#pragma unroll
                for (int j = 0; j < 4; j++) acc[i][j] += a[i] * bb[j];
        }
        __syncthreads();
    }

    const float scale = rsqrtf((float)CC);
#pragma unroll
    for (int i = 0; i < 4; i++) {
        float* sp = g_s + ((size_t)b * NN + n0 + ty * 4 + i) * NN + m0 + tx * 4;
        float4 v = make_float4(acc[i][0] * scale, acc[i][1] * scale,
                               acc[i][2] * scale, acc[i][3] * scale);
        *reinterpret_cast<float4*>(sp) = v;
    }
}

// ============================================================
// Kernel 4: row softmax over m (4096). One block per (b, n) row.
// Row held fully in registers: 16 values per thread.
// ============================================================
__global__ void softmax_kernel() {
    int b = blockIdx.y;
    int row = blockIdx.x;
    float* p = g_s + ((size_t)b * NN + row) * NN;
    int tid = threadIdx.x;

    float vals[16];
    float mx = -1e30f;
#pragma unroll
    for (int i = 0; i < 16; i++) {
        vals[i] = p[tid + i * 256];
        mx = fmaxf(mx, vals[i]);
    }
    // block max
    __shared__ float sred[64];
#pragma unroll
    for (int off = 16; off > 0; off >>= 1)
        mx = fmaxf(mx, __shfl_xor_sync(0xffffffffu, mx, off));
    if ((tid & 31) == 0) sred[tid >> 5] = mx;
    __syncthreads();
    if (tid < 32) {
        float v = (tid < 8) ? sred[tid] : -1e30f;
#pragma unroll
        for (int off = 4; off > 0; off >>= 1)
            v = fmaxf(v, __shfl_xor_sync(0xffffffffu, v, off));
        if (tid == 0) sred[32] = v;
    }
    __syncthreads();
    mx = sred[32];

    float sum = 0.f;
#pragma unroll
    for (int i = 0; i < 16; i++) {
        vals[i] = __expf(vals[i] - mx);
        sum += vals[i];
    }
#pragma unroll
    for (int off = 16; off > 0; off >>= 1)
        sum += __shfl_xor_sync(0xffffffffu, sum, off);
    if ((tid & 31) == 0) sred[tid >> 5] = sum;
    __syncthreads();
    if (tid < 32) {
        float v = (tid < 8) ? sred[tid] : 0.f;
#pragma unroll
        for (int off = 4; off > 0; off >>= 1)
            v += __shfl_xor_sync(0xffffffffu, v, off);
        if (tid == 0) sred[33] = v;
    }
    __syncthreads();
    float inv = 1.f / sred[33];
#pragma unroll
    for (int i = 0; i < 16; i++) p[tid + i * 256] = vals[i] * inv;
}

// ============================================================
// Kernel 5: AV GEMM. att[b][c][n] = sum_m k[b][c][m] * P[b][n][m]
// Reduction runs along the contiguous dim of both operands, so tiles are
// staged transposed in smem. K-chunk 32.
// ============================================================
__global__ void av_gemm_kernel() {
    int b = blockIdx.z;
    int c0b = blockIdx.y * 64;
    int n0 = blockIdx.x * 64;

    __shared__ float Kt[32][68];  // [mm][c]
    __shared__ float Pt[32][68];  // [mm][n]

    int tid = threadIdx.x;
    int tx = tid & 15, ty = tid >> 4;
    float acc[4][4] = {};

    const float* kp = g_k + (size_t)b * CC * NN;
    const float* pp = g_s + (size_t)b * NN * NN;

    for (int m0 = 0; m0 < NN; m0 += 32) {
        int mm = tid & 31, ib = tid >> 5;
#pragma unroll
        for (int r = 0; r < 8; r++) {
            int idx = ib + r * 8;  // 0..63
            Kt[mm][idx] = kp[(size_t)(c0b + idx) * NN + m0 + mm];
            Pt[mm][idx] = pp[(size_t)(n0 + idx) * NN + m0 + mm];
        }
        __syncthreads();
#pragma unroll
        for (int mm2 = 0; mm2 < 32; mm2++) {
            float4 a4 = *reinterpret_cast<const float4*>(&Kt[mm2][ty * 4]);
            float4 b4 = *reinterpret_cast<const float4*>(&Pt[mm2][tx * 4]);
            float a[4] = {a4.x, a4.y, a4.z, a4.w};
            float bb[4] = {b4.x, b4.y, b4.z, b4.w};
#pragma unroll
            for (int i = 0; i < 4; i++)
#pragma unroll
                for (int j = 0; j < 4; j++) acc[i][j] += a[i] * bb[j];
        }
        __syncthreads();
    }

#pragma unroll
    for (int i = 0; i < 4; i++) {
        int c = c0b + ty * 4 + i;
        float* op = g_att + ((size_t)b * CC + c) * NN + n0 + tx * 4;
        float4 v = make_float4(acc[i][0], acc[i][1], acc[i][2], acc[i][3]);
        *reinterpret_cast<float4*>(op) = v;
    }
}

// ============================================================
// Kernel 6: proj GEMM + bias + residual.
//   out[b][o][n] = x[b][o][n] + pb[o] + sum_c pw[o][c] * att[b][c][n]
// ============================================================
__global__ void proj_gemm_kernel(const float* __restrict__ x,
                                 const float* __restrict__ pw,
                                 const float* __restrict__ pb,
                                 float* __restrict__ out) {
    int b = blockIdx.z;
    int n0 = blockIdx.x * 64;
    int o0 = blockIdx.y * 64;

    __shared__ float Ws[16][68];  // [kk][o]
    __shared__ float As[16][68];  // [kk][n]

    int tid = threadIdx.x;
    int tx = tid & 15, ty = tid >> 4;
    float acc[4][4] = {};

    const float* ap = g_att + (size_t)b * CC * NN;

    for (int c0 = 0; c0 < CC; c0 += 16) {
        {
            int kk = tid & 15, ob = tid >> 4;
#pragma unroll
            for (int r = 0; r < 4; r++) {
                int o = o0 + ob + r * 16;
                Ws[kk][ob + r * 16] = pw[(size_t)o * CC + c0 + kk];
            }
        }
        {
            int nj = tid & 63, kbase = tid >> 6;
#pragma unroll
            for (int r = 0; r < 4; r++) {
                int kk = kbase + r * 4;
                As[kk][nj] = ap[(size_t)(c0 + kk) * NN + n0 + nj];
            }
        }
        __syncthreads();
#pragma unroll
        for (int kk = 0; kk < 16; kk++) {
            float4 a4 = *reinterpret_cast<const float4*>(&Ws[kk][ty * 4]);
            float4 b4 = *reinterpret_cast<const float4*>(&As[kk][tx * 4]);
            float a[4] = {a4.x, a4.y, a4.z, a4.w};
            float bb[4] = {b4.x, b4.y, b4.z, b4.w};
#pragma unroll
            for (int i = 0; i < 4; i++)
#pragma unroll
                for (int j = 0; j < 4; j++) acc[i][j] += a[i] * bb[j];
        }
        __syncthreads();
    }

#pragma unroll
    for (int i = 0; i < 4; i++) {
        int o = o0 + ty * 4 + i;
        float bv = pb[o];
        size_t base = ((size_t)b * CC + o) * NN + n0 + tx * 4;
        float4 xv = *reinterpret_cast<const float4*>(&x[base]);
        float4 v = make_float4(acc[i][0] + bv + xv.x, acc[i][1] + bv + xv.y,
                               acc[i][2] + bv + xv.z, acc[i][3] + bv + xv.w);
        *reinterpret_cast<float4*>(&out[base]) = v;
    }
}

// ============================================================
// launch
// ============================================================
extern "C" void kernel_launch(void* const* d_in, const int* in_sizes, int n_in,
                              void* d_out, int out_size) {
    const float* x     = (const float*)d_in[0];
    const float* gamma = (const float*)d_in[1];
    const float* beta  = (const float*)d_in[2];
    const float* q_w   = (const float*)d_in[3];
    const float* q_b   = (const float*)d_in[4];
    const float* k_w   = (const float*)d_in[5];
    const float* k_b   = (const float*)d_in[6];
    const float* p_w   = (const float*)d_in[7];
    const float* p_b   = (const float*)d_in[8];
    float* out = (float*)d_out;

    (void)in_sizes; (void)n_in; (void)out_size;

    // 1. GroupNorm stats
    gn_stats_kernel<<<dim3(BATCH, GG), 256>>>(x);

    // 2. q/k projections with fused normalization
    qk_gemm_kernel<<<dim3(NN / 64, CC / 64, BATCH * 2), 256>>>(
        x, q_w, q_b, k_w, k_b, gamma, beta);

    // 3. scores = scale * q^T k
    scores_gemm_kernel<<<dim3(NN / 64, NN / 64, BATCH), 256>>>();

    // 4. softmax over last dim
    softmax_kernel<<<dim3(NN, BATCH), 256>>>();

    // 5. att = v @ attn^T  (v = k)
    av_gemm_kernel<<<dim3(NN / 64, CC / 64, BATCH), 256>>>();

    // 6. out = x + proj(att)
    proj_gemm_kernel<<<dim3(NN / 64, CC / 64, BATCH), 256>>>(x, p_w, p_b, out);
}

// round 3
// speedup vs baseline: 3.6540x; 3.6540x over previous
#include <cuda_runtime.h>
#include <math.h>

#define BATCH 8
#define CC 512
#define NN 4096
#define GG 32
#define CPG 16

// ---- scratch (static device globals; allowed by harness rules) ----
__device__ float g_q[(size_t)BATCH * CC * NN];      // 64 MB
__device__ float g_k[(size_t)BATCH * CC * NN];      // 64 MB
__device__ float g_att[(size_t)BATCH * CC * NN];    // 64 MB
__device__ float g_s[(size_t)BATCH * NN * NN];      // 512 MB (scores / probs in place)
__device__ float g_stats[BATCH * GG * 2];           // mean, rstd per (b, g)

// ============================================================
// helpers: tf32 convert + m16n8k8 tf32 mma
// ============================================================
__device__ __forceinline__ unsigned f2tf(float f) {
    unsigned u;
    asm("cvt.rna.tf32.f32 %0, %1;" : "=r"(u) : "f"(f));
    return u;
}

__device__ __forceinline__ void mma8(float* c, unsigned a0, unsigned a1, unsigned a2, unsigned a3,
                                     unsigned b0, unsigned b1) {
    asm volatile(
        "mma.sync.aligned.m16n8k8.row.col.f32.tf32.tf32.f32 "
        "{%0,%1,%2,%3},{%4,%5,%6,%7},{%8,%9},{%0,%1,%2,%3};"
        : "+f"(c[0]), "+f"(c[1]), "+f"(c[2]), "+f"(c[3])
        : "r"(a0), "r"(a1), "r"(a2), "r"(a3), "r"(b0), "r"(b1));
}

// ============================================================
// Kernel 1: GroupNorm statistics. One block per (b, g).
// ============================================================
__global__ void gn_stats_kernel(const float* __restrict__ x) {
    int b = blockIdx.x, g = blockIdx.y;
    const float* xp = x + ((size_t)(b * CC) + g * CPG) * NN;
    float s = 0.f, s2 = 0.f;
    for (int i = threadIdx.x; i < CPG * NN; i += 256) {
        float v = xp[i];
        s += v;
        s2 += v * v;
    }
    __shared__ float sh[256], sh2[256];
    sh[threadIdx.x] = s;
    sh2[threadIdx.x] = s2;
    __syncthreads();
    for (int off = 128; off > 0; off >>= 1) {
        if (threadIdx.x < off) {
            sh[threadIdx.x] += sh[threadIdx.x + off];
            sh2[threadIdx.x] += sh2[threadIdx.x + off];
        }
        __syncthreads();
    }
    if (threadIdx.x == 0) {
        const float inv = 1.f / (float)(CPG * NN);
        float mu = sh[0] * inv;
        float var = sh2[0] * inv - mu * mu;
        g_stats[(b * GG + g) * 2 + 0] = mu;
        g_stats[(b * GG + g) * 2 + 1] = rsqrtf(var + 1e-6f);
    }
}

// ============================================================
// Kernel 2: q/k projection, tensor-core.
//   out[o][n] = bias[o] + sum_c W[o][c] * norm(x[c][n])
// A = W (MK smem: [o][c], c contiguous), B = norm(x) (KM smem: [c][n]).
// Block tile 128(o) x 128(n), 8 warps of 64x32, K-chunk 32.
// ============================================================
__global__ __launch_bounds__(256, 2) void qk_mma_kernel(
        const float* __restrict__ x,
        const float* __restrict__ qw, const float* __restrict__ qb,
        const float* __restrict__ kw, const float* __restrict__ kb,
        const float* __restrict__ gamma, const float* __restrict__ beta) {
    int b = blockIdx.z >> 1, which = blockIdx.z & 1;
    const float* w = which ? kw : qw;
    const float* bias = which ? kb : qb;
    float* out = which ? g_k : g_q;
    int o_blk = blockIdx.y * 128, n_blk = blockIdx.x * 128;

    __shared__ __align__(16) unsigned As[128][36];
    __shared__ __align__(16) unsigned Bs[32][136];

    int tid = threadIdx.x, lane = tid & 31, wid = tid >> 5;
    int gid = lane >> 2, tig = lane & 3;
    int wm = (wid & 1) * 64, wn = (wid >> 1) * 32;
    float acc[4][4][4] = {};

    const float* xb = x + (size_t)b * CC * NN;
    int rb = tid >> 5, c4 = (tid & 31) * 4;
    int oa = tid >> 3, ca4 = (tid & 7) * 4;

    for (int c0 = 0; c0 < CC; c0 += 32) {
#pragma unroll
        for (int r = 0; r < 4; r++) {
            int o = oa + r * 32;
            float4 wv = *(const float4*)(w + (size_t)(o_blk + o) * CC + c0 + ca4);
            uint4 t = make_uint4(f2tf(wv.x), f2tf(wv.y), f2tf(wv.z), f2tf(wv.w));
            *(uint4*)&As[o][ca4] = t;
        }
#pragma unroll
        for (int r = 0; r < 4; r++) {
            int row = rb + r * 8;
            int c = c0 + row, g = c >> 4;
            float rstd = g_stats[(b * GG + g) * 2 + 1];
            float ga = gamma[c] * rstd;
            float be = beta[c] - g_stats[(b * GG + g) * 2 + 0] * ga;
            float4 xv = *(const float4*)(xb + (size_t)c * NN + n_blk + c4);
            uint4 t = make_uint4(f2tf(fmaf(xv.x, ga, be)), f2tf(fmaf(xv.y, ga, be)),
                                 f2tf(fmaf(xv.z, ga, be)), f2tf(fmaf(xv.w, ga, be)));
            *(uint4*)&Bs[row][c4] = t;
        }
        __syncthreads();
#pragma unroll
        for (int ks = 0; ks < 4; ks++) {
            int k0 = ks * 8;
            unsigned a[4][4], bf[4][2];
#pragma unroll
            for (int mi = 0; mi < 4; mi++) {
                int m = wm + mi * 16 + gid;
                a[mi][0] = As[m][k0 + tig];
                a[mi][1] = As[m + 8][k0 + tig];
                a[mi][2] = As[m][k0 + tig + 4];
                a[mi][3] = As[m + 8][k0 + tig + 4];
            }
#pragma unroll
            for (int ni = 0; ni < 4; ni++) {
                int n = wn + ni * 8 + gid;
                bf[ni][0] = Bs[k0 + tig][n];
                bf[ni][1] = Bs[k0 + tig + 4][n];
            }
#pragma unroll
            for (int mi = 0; mi < 4; mi++)
#pragma unroll
                for (int ni = 0; ni < 4; ni++)
                    mma8(acc[mi][ni], a[mi][0], a[mi][1], a[mi][2], a[mi][3],
                         bf[ni][0], bf[ni][1]);
        }
        __syncthreads();
    }

#pragma unroll
    for (int mi = 0; mi < 4; mi++) {
        int o = o_blk + wm + mi * 16 + gid;
        float bv0 = bias[o], bv1 = bias[o + 8];
        float* p0 = out + ((size_t)b * CC + o) * NN + n_blk;
        float* p1 = p0 + (size_t)8 * NN;
#pragma unroll
        for (int ni = 0; ni < 4; ni++) {
            int cb = wn + ni * 8 + tig * 2;
            *(float2*)(p0 + cb) = make_float2(acc[mi][ni][0] + bv0, acc[mi][ni][1] + bv0);
            *(float2*)(p1 + cb) = make_float2(acc[mi][ni][2] + bv1, acc[mi][ni][3] + bv1);
        }
    }
}

// ============================================================
// Kernel 3: scores, tensor-core.
//   S[n][m] = scale * sum_c q[c][n] * k[c][m]
// Both operands KM ([c][spatial], spatial contiguous) — direct copies.
// ============================================================
__global__ __launch_bounds__(256, 2) void scores_mma_kernel() {
    int b = blockIdx.z;
    int n_blk = blockIdx.y * 128;   // output rows (q spatial)
    int m_blk = blockIdx.x * 128;   // output cols (k spatial)

    __shared__ __align__(16) unsigned As[32][136];
    __shared__ __align__(16) unsigned Bs[32][136];

    int tid = threadIdx.x, lane = tid & 31, wid = tid >> 5;
    int gid = lane >> 2, tig = lane & 3;
    int wm = (wid & 1) * 64, wn = (wid >> 1) * 32;
    float acc[4][4][4] = {};

    const float* qp = g_q + (size_t)b * CC * NN;
    const float* kp = g_k + (size_t)b * CC * NN;
    int rb = tid >> 5, c4 = (tid & 31) * 4;

    for (int c0 = 0; c0 < CC; c0 += 32) {
#pragma unroll
        for (int r = 0; r < 4; r++) {
            int row = rb + r * 8;
            float4 qa = *(const float4*)(qp + (size_t)(c0 + row) * NN + n_blk + c4);
            float4 ka = *(const float4*)(kp + (size_t)(c0 + row) * NN + m_blk + c4);
            *(uint4*)&As[row][c4] = make_uint4(f2tf(qa.x), f2tf(qa.y), f2tf(qa.z), f2tf(qa.w));
            *(uint4*)&Bs[row][c4] = make_uint4(f2tf(ka.x), f2tf(ka.y), f2tf(ka.z), f2tf(ka.w));
        }
        __syncthreads();
#pragma unroll
        for (int ks = 0; ks < 4; ks++) {
            int k0 = ks * 8;
            unsigned a[4][4], bf[4][2];
#pragma unroll
            for (int mi = 0; mi < 4; mi++) {
                int m = wm + mi * 16 + gid;
                a[mi][0] = As[k0 + tig][m];
                a[mi][1] = As[k0 + tig][m + 8];
                a[mi][2] = As[k0 + tig + 4][m];
                a[mi][3] = As[k0 + tig + 4][m + 8];
            }
#pragma unroll
            for (int ni = 0; ni < 4; ni++) {
                int n = wn + ni * 8 + gid;
                bf[ni][0] = Bs[k0 + tig][n];
                bf[ni][1] = Bs[k0 + tig + 4][n];
            }
#pragma unroll
            for (int mi = 0; mi < 4; mi++)
#pragma unroll
                for (int ni = 0; ni < 4; ni++)
                    mma8(acc[mi][ni], a[mi][0], a[mi][1], a[mi][2], a[mi][3],
                         bf[ni][0], bf[ni][1]);
        }
        __syncthreads();
    }

    const float scale = rsqrtf((float)CC);
#pragma unroll
    for (int mi = 0; mi < 4; mi++) {
        int rrow = n_blk + wm + mi * 16 + gid;
        float* p0 = g_s + ((size_t)b * NN + rrow) * NN + m_blk;
        float* p1 = p0 + (size_t)8 * NN;
#pragma unroll
        for (int ni = 0; ni < 4; ni++) {
            int cb = wn + ni * 8 + tig * 2;
            *(float2*)(p0 + cb) = make_float2(acc[mi][ni][0] * scale, acc[mi][ni][1] * scale);
            *(float2*)(p1 + cb) = make_float2(acc[mi][ni][2] * scale, acc[mi][ni][3] * scale);
        }
    }
}

// ============================================================
// Kernel 4: row softmax over m (4096). Unchanged (85% of HBM roof already).
// ============================================================
__global__ void softmax_kernel() {
    int b = blockIdx.y;
    int row = blockIdx.x;
    float* p = g_s + ((size_t)b * NN + row) * NN;
    int tid = threadIdx.x;

    float vals[16];
    float mx = -1e30f;
#pragma unroll
    for (int i = 0; i < 16; i++) {
        vals[i] = p[tid + i * 256];
        mx = fmaxf(mx, vals[i]);
    }
    __shared__ float sred[64];
#pragma unroll
    for (int off = 16; off > 0; off >>= 1)
        mx = fmaxf(mx, __shfl_xor_sync(0xffffffffu, mx, off));
    if ((tid & 31) == 0) sred[tid >> 5] = mx;
    __syncthreads();
    if (tid < 32) {
        float v = (tid < 8) ? sred[tid] : -1e30f;
#pragma unroll
        for (int off = 4; off > 0; off >>= 1)
            v = fmaxf(v, __shfl_xor_sync(0xffffffffu, v, off));
        if (tid == 0) sred[32] = v;
    }
    __syncthreads();
    mx = sred[32];

    float sum = 0.f;
#pragma unroll
    for (int i = 0; i < 16; i++) {
        vals[i] = __expf(vals[i] - mx);
        sum += vals[i];
    }
#pragma unroll
    for (int off = 16; off > 0; off >>= 1)
        sum += __shfl_xor_sync(0xffffffffu, sum, off);
    if ((tid & 31) == 0) sred[tid >> 5] = sum;
    __syncthreads();
    if (tid < 32) {
        float v = (tid < 8) ? sred[tid] : 0.f;
#pragma unroll
        for (int off = 4; off > 0; off >>= 1)
            v += __shfl_xor_sync(0xffffffffu, v, off);
        if (tid == 0) sred[33] = v;
    }
    __syncthreads();
    float inv = 1.f / sred[33];
#pragma unroll
    for (int i = 0; i < 16; i++) p[tid + i * 256] = vals[i] * inv;
}

// ============================================================
// Kernel 5: AV, tensor-core.
//   att[c][n] = sum_m k[c][m] * P[n][m]
// Both operands MK ([row][m], m contiguous) — direct copies, K-dim = m.
// ============================================================
__global__ __launch_bounds__(256, 2) void av_mma_kernel() {
    int b = blockIdx.z;
    int c_blk = blockIdx.y * 128;   // output rows (channels)
    int n_blk = blockIdx.x * 128;   // output cols (q spatial)

    __shared__ __align__(16) unsigned As[128][36];  // k [c][m]
    __shared__ __align__(16) unsigned Bs[128][36];  // P [n][m]

    int tid = threadIdx.x, lane = tid & 31, wid = tid >> 5;
    int gid = lane >> 2, tig = lane & 3;
    int wm = (wid & 1) * 64, wn = (wid >> 1) * 32;
    float acc[4][4][4] = {};

    const float* kp = g_k + (size_t)b * CC * NN;
    const float* pp = g_s + (size_t)b * NN * NN;
    int ra = tid >> 3, m4 = (tid & 7) * 4;

    for (int m0 = 0; m0 < NN; m0 += 32) {
#pragma unroll
        for (int r = 0; r < 4; r++) {
            int row = ra + r * 32;
            float4 kv = *(const float4*)(kp + (size_t)(c_blk + row) * NN + m0 + m4);
            float4 pv = *(const float4*)(pp + (size_t)(n_blk + row) * NN + m0 + m4);
            *(uint4*)&As[row][m4] = make_uint4(f2tf(kv.x), f2tf(kv.y), f2tf(kv.z), f2tf(kv.w));
            *(uint4*)&Bs[row][m4] = make_uint4(f2tf(pv.x), f2tf(pv.y), f2tf(pv.z), f2tf(pv.w));
        }
        __syncthreads();
#pragma unroll
        for (int ks = 0; ks < 4; ks++) {
            int k0 = ks * 8;
            unsigned a[4][4], bf[4][2];
#pragma unroll
            for (int mi = 0; mi < 4; mi++) {
                int m = wm + mi * 16 + gid;
                a[mi][0] = As[m][k0 + tig];
                a[mi][1] = As[m + 8][k0 + tig];
                a[mi][2] = As[m][k0 + tig + 4];
                a[mi][3] = As[m + 8][k0 + tig + 4];
            }
#pragma unroll
            for (int ni = 0; ni < 4; ni++) {
                int n = wn + ni * 8 + gid;
                bf[ni][0] = Bs[n][k0 + tig];
                bf[ni][1] = Bs[n][k0 + tig + 4];
            }
#pragma unroll
            for (int mi = 0; mi < 4; mi++)
#pragma unroll
                for (int ni = 0; ni < 4; ni++)
                    mma8(acc[mi][ni], a[mi][0], a[mi][1], a[mi][2], a[mi][3],
                         bf[ni][0], bf[ni][1]);
        }
        __syncthreads();
    }

#pragma unroll
    for (int mi = 0; mi < 4; mi++) {
        int c = c_blk + wm + mi * 16 + gid;
        float* p0 = g_att + ((size_t)b * CC + c) * NN + n_blk;
        float* p1 = p0 + (size_t)8 * NN;
#pragma unroll
        for (int ni = 0; ni < 4; ni++) {
            int cb = wn + ni * 8 + tig * 2;
            *(float2*)(p0 + cb) = make_float2(acc[mi][ni][0], acc[mi][ni][1]);
            *(float2*)(p1 + cb) = make_float2(acc[mi][ni][2], acc[mi][ni][3]);
        }
    }
}

// ============================================================
// Kernel 6: proj + bias + residual, tensor-core.
//   out[o][n] = x[o][n] + pb[o] + sum_c pw[o][c] * att[c][n]
// ============================================================
__global__ __launch_bounds__(256, 2) void proj_mma_kernel(
        const float* __restrict__ x,
        const float* __restrict__ pw, const float* __restrict__ pb,
        float* __restrict__ out) {
    int b = blockIdx.z;
    int o_blk = blockIdx.y * 128, n_blk = blockIdx.x * 128;

    __shared__ __align__(16) unsigned As[128][36];
    __shared__ __align__(16) unsigned Bs[32][136];

    int tid = threadIdx.x, lane = tid & 31, wid = tid >> 5;
    int gid = lane >> 2, tig = lane & 3;
    int wm = (wid & 1) * 64, wn = (wid >> 1) * 32;
    float acc[4][4][4] = {};

    const float* ap = g_att + (size_t)b * CC * NN;
    int rb = tid >> 5, c4 = (tid & 31) * 4;
    int oa = tid >> 3, ca4 = (tid & 7) * 4;

    for (int c0 = 0; c0 < CC; c0 += 32) {
#pragma unroll
        for (int r = 0; r < 4; r++) {
            int o = oa + r * 32;
            float4 wv = *(const float4*)(pw + (size_t)(o_blk + o) * CC + c0 + ca4);
            *(uint4*)&As[o][ca4] = make_uint4(f2tf(wv.x), f2tf(wv.y), f2tf(wv.z), f2tf(wv.w));
        }
#pragma unroll
        for (int r = 0; r < 4; r++) {
            int row = rb + r * 8;
            float4 av = *(const float4*)(ap + (size_t)(c0 + row) * NN + n_blk + c4);
            *(uint4*)&Bs[row][c4] = make_uint4(f2tf(av.x), f2tf(av.y), f2tf(av.z), f2tf(av.w));
        }
        __syncthreads();
#pragma unroll
        for (int ks = 0; ks < 4; ks++) {
            int k0 = ks * 8;
            unsigned a[4][4], bf[4][2];
#pragma unroll
            for (int mi = 0; mi < 4; mi++) {
                int m = wm + mi * 16 + gid;
                a[mi][0] = As[m][k0 + tig];
                a[mi][1] = As[m + 8][k0 + tig];
                a[mi][2] = As[m][k0 + tig + 4];
                a[mi][3] = As[m + 8][k0 + tig + 4];
            }
#pragma unroll
            for (int ni = 0; ni < 4; ni++) {
                int n = wn + ni * 8 + gid;
                bf[ni][0] = Bs[k0 + tig][n];
                bf[ni][1] = Bs[k0 + tig + 4][n];
            }
#pragma unroll
            for (int mi = 0; mi < 4; mi++)
#pragma unroll
                for (int ni = 0; ni < 4; ni++)
                    mma8(acc[mi][ni], a[mi][0], a[mi][1], a[mi][2], a[mi][3],
                         bf[ni][0], bf[ni][1]);
        }
        __syncthreads();
    }

#pragma unroll
    for (int mi = 0; mi < 4; mi++) {
        int o = o_blk + wm + mi * 16 + gid;
        float bv0 = pb[o], bv1 = pb[o + 8];
        size_t base0 = ((size_t)b * CC + o) * NN + n_blk;
        size_t base1 = base0 + (size_t)8 * NN;
#pragma unroll
        for (int ni = 0; ni < 4; ni++) {
            int cb = wn + ni * 8 + tig * 2;
            float2 x0 = *(const float2*)(x + base0 + cb);
            float2 x1 = *(const float2*)(x + base1 + cb);
            *(float2*)(out + base0 + cb) =
                make_float2(acc[mi][ni][0] + bv0 + x0.x, acc[mi][ni][1] + bv0 + x0.y);
            *(float2*)(out + base1 + cb) =
                make_float2(acc[mi][ni][2] + bv1 + x1.x, acc[mi][ni][3] + bv1 + x1.y);
        }
    }
}

// ============================================================
// launch
// ============================================================
extern "C" void kernel_launch(void* const* d_in, const int* in_sizes, int n_in,
                              void* d_out, int out_size) {
    const float* x     = (const float*)d_in[0];
    const float* gamma = (const float*)d_in[1];
    const float* beta  = (const float*)d_in[2];
    const float* q_w   = (const float*)d_in[3];
    const float* q_b   = (const float*)d_in[4];
    const float* k_w   = (const float*)d_in[5];
    const float* k_b   = (const float*)d_in[6];
    const float* p_w   = (const float*)d_in[7];
    const float* p_b   = (const float*)d_in[8];
    float* out = (float*)d_out;

    (void)in_sizes; (void)n_in; (void)out_size;

    gn_stats_kernel<<<dim3(BATCH, GG), 256>>>(x);

    qk_mma_kernel<<<dim3(NN / 128, CC / 128, BATCH * 2), 256>>>(
        x, q_w, q_b, k_w, k_b, gamma, beta);

    scores_mma_kernel<<<dim3(NN / 128, NN / 128, BATCH), 256>>>();

    softmax_kernel<<<dim3(NN, BATCH), 256>>>();

    av_mma_kernel<<<dim3(NN / 128, CC / 128, BATCH), 256>>>();

    proj_mma_kernel<<<dim3(NN / 128, CC / 128, BATCH), 256>>>(x, p_w, p_b, out);
}

// round 4
// speedup vs baseline: 3.9320x; 1.0761x over previous
#include <cuda_runtime.h>
#include <math.h>

#define BATCH 8
#define CC 512
#define NN 4096
#define GG 32
#define CPG 16

// ---- scratch (static device globals; allowed by harness rules) ----
__device__ float g_q[(size_t)BATCH * CC * NN];      // 64 MB
__device__ float g_k[(size_t)BATCH * CC * NN];      // 64 MB
__device__ float g_att[(size_t)BATCH * CC * NN];    // 64 MB (rna(x), later att)
__device__ float g_s[(size_t)BATCH * NN * NN];      // 512 MB (scores / probs in place)
__device__ float g_stats[BATCH * GG * 2];           // mean, rstd per (b, g)
__device__ float g_qwf[(size_t)BATCH * CC * CC];    // folded q weights per batch
__device__ float g_kwf[(size_t)BATCH * CC * CC];    // folded k weights per batch
__device__ float g_pwf[(size_t)CC * CC];            // rna(proj weights)
__device__ float g_qbf[BATCH * CC];
__device__ float g_kbf[BATCH * CC];

// ============================================================
// helpers
// ============================================================
__device__ __forceinline__ unsigned f2tf(float f) {
    unsigned u;
    asm("cvt.rna.tf32.f32 %0, %1;" : "=r"(u) : "f"(f));
    return u;
}
__device__ __forceinline__ float rna(float f) { return __uint_as_float(f2tf(f)); }

__device__ __forceinline__ void mma8(float* c, unsigned a0, unsigned a1, unsigned a2, unsigned a3,
                                     unsigned b0, unsigned b1) {
    asm volatile(
        "mma.sync.aligned.m16n8k8.row.col.f32.tf32.tf32.f32 "
        "{%0,%1,%2,%3},{%4,%5,%6,%7},{%8,%9},{%0,%1,%2,%3};"
        : "+f"(c[0]), "+f"(c[1]), "+f"(c[2]), "+f"(c[3])
        : "r"(a0), "r"(a1), "r"(a2), "r"(a3), "r"(b0), "r"(b1));
}

__device__ __forceinline__ void cp16(void* smem_dst, const void* gsrc) {
    unsigned s = (unsigned)__cvta_generic_to_shared(smem_dst);
    asm volatile("cp.async.cg.shared.global [%0], [%1], 16;" :: "r"(s), "l"(gsrc));
}
#define CP_COMMIT asm volatile("cp.async.commit_group;")
#define CP_WAIT1 asm volatile("cp.async.wait_group 1;")
#define CP_WAIT0 asm volatile("cp.async.wait_group 0;")

// ============================================================
// Kernel 1: GroupNorm statistics. One block per (b, g).
// ============================================================
__global__ void gn_stats_kernel(const float* __restrict__ x) {
    int b = blockIdx.x, g = blockIdx.y;
    const float* xp = x + ((size_t)(b * CC) + g * CPG) * NN;
    float s = 0.f, s2 = 0.f;
    for (int i = threadIdx.x; i < CPG * NN; i += 256) {
        float v = xp[i];
        s += v;
        s2 += v * v;
    }
    __shared__ float sh[256], sh2[256];
    sh[threadIdx.x] = s;
    sh2[threadIdx.x] = s2;
    __syncthreads();
    for (int off = 128; off > 0; off >>= 1) {
        if (threadIdx.x < off) {
            sh[threadIdx.x] += sh[threadIdx.x + off];
            sh2[threadIdx.x] += sh2[threadIdx.x + off];
        }
        __syncthreads();
    }
    if (threadIdx.x == 0) {
        const float inv = 1.f / (float)(CPG * NN);
        float mu = sh[0] * inv;
        float var = sh2[0] * inv - mu * mu;
        g_stats[(b * GG + g) * 2 + 0] = mu;
        g_stats[(b * GG + g) * 2 + 1] = rsqrtf(var + 1e-6f);
    }
}

// ============================================================
// Kernel 2: fold GroupNorm + softmax-scale into weights/biases, rna-round.
// grid (BATCH, 4): 128 output channels per block.
// ============================================================
__global__ void fold_kernel(const float* __restrict__ qw, const float* __restrict__ qb,
                            const float* __restrict__ kw, const float* __restrict__ kb,
                            const float* __restrict__ pw,
                            const float* __restrict__ gamma, const float* __restrict__ beta) {
    int b = blockIdx.x, o0 = blockIdx.y * 128;
    __shared__ float ga[CC], be[CC];
    for (int c = threadIdx.x; c < CC; c += 256) {
        int g = c >> 4;
        float mu = g_stats[(b * GG + g) * 2 + 0];
        float rstd = g_stats[(b * GG + g) * 2 + 1];
        float gg = gamma[c] * rstd;
        ga[c] = gg;
        be[c] = beta[c] - mu * gg;
    }
    __syncthreads();
    const float s = rsqrtf((float)CC);
    for (int idx = threadIdx.x; idx < 128 * CC; idx += 256) {
        int o = o0 + (idx >> 9), c = idx & (CC - 1);
        float w1 = qw[(size_t)o * CC + c] * ga[c] * s;
        float w2 = kw[(size_t)o * CC + c] * ga[c];
        g_qwf[((size_t)b * CC + o) * CC + c] = rna(w1);
        g_kwf[((size_t)b * CC + o) * CC + c] = rna(w2);
    }
    // biases: thread pairs split the 512-dot
    {
        int o = o0 + (threadIdx.x >> 1);
        int h = (threadIdx.x & 1) * 256;
        float sq = 0.f, sk = 0.f;
        for (int c = h; c < h + 256; c++) {
            sq += qw[(size_t)o * CC + c] * be[c];
            sk += kw[(size_t)o * CC + c] * be[c];
        }
        sq += __shfl_xor_sync(0xffffffffu, sq, 1);
        sk += __shfl_xor_sync(0xffffffffu, sk, 1);
        if ((threadIdx.x & 1) == 0) {
            g_qbf[b * CC + o] = (qb[o] + sq) * s;
            g_kbf[b * CC + o] = kb[o] + sk;
        }
    }
    if (b == 0) {
        for (int idx = threadIdx.x; idx < 128 * CC; idx += 256) {
            int o = o0 + (idx >> 9), c = idx & (CC - 1);
            g_pwf[(size_t)o * CC + c] = rna(pw[(size_t)o * CC + c]);
        }
    }
}

// ============================================================
// Kernel 3: rna(x) -> g_att (consumed by qk GEMM, overwritten later by AV).
// ============================================================
__global__ void xcvt_kernel(const float* __restrict__ x) {
    size_t i = ((size_t)blockIdx.x * 256 + threadIdx.x) * 4;
    float4 v = *(const float4*)(x + i);
    uint4 t = make_uint4(f2tf(v.x), f2tf(v.y), f2tf(v.z), f2tf(v.w));
    *(uint4*)&g_att[i] = t;
}

// ============================================================
// Kernel 4: q/k projection, pure GEMM, cp.async double-buffered.
//   out[o][n] = b'[o] + sum_c W'[o][c] * xr[c][n]    (all tf32 already)
// ============================================================
__global__ __launch_bounds__(256, 2) void qk_mma_kernel() {
    int b = blockIdx.z >> 1, which = blockIdx.z & 1;
    const float* w = (which ? g_kwf : g_qwf) + (size_t)b * CC * CC;
    const float* bias = (which ? g_kbf : g_qbf) + b * CC;
    float* out = which ? g_k : g_q;
    int o_blk = blockIdx.y * 128, n_blk = blockIdx.x * 128;

    extern __shared__ unsigned sm[];
    unsigned* Asb = sm;                 // [2][128][36]
    unsigned* Bsb = sm + 2 * 128 * 36;  // [2][32][136]
#define AS4(st, i, j) Asb[(st) * 4608 + (i) * 36 + (j)]
#define BS4(st, i, j) Bsb[(st) * 4352 + (i) * 136 + (j)]

    int tid = threadIdx.x, lane = tid & 31, wid = tid >> 5;
    int gid = lane >> 2, tig = lane & 3;
    int wm = (wid & 1) * 64, wn = (wid >> 1) * 32;
    float acc[4][4][4] = {};

    const float* xb = g_att + (size_t)b * CC * NN;
    int rb = tid >> 5, c4 = (tid & 31) * 4;
    int oa = tid >> 3, ca4 = (tid & 7) * 4;

    const int NCH = CC / 32;  // 16
#define QK_LOAD(st, c0)                                                              \
    {                                                                                \
        _Pragma("unroll") for (int r = 0; r < 4; r++) {                              \
            int o = oa + r * 32;                                                     \
            cp16(&AS4(st, o, ca4), w + (size_t)(o_blk + o) * CC + (c0) + ca4);       \
        }                                                                            \
        _Pragma("unroll") for (int r = 0; r < 4; r++) {                              \
            int row = rb + r * 8;                                                    \
            cp16(&BS4(st, row, c4), xb + (size_t)((c0) + row) * NN + n_blk + c4);    \
        }                                                                            \
    }

    QK_LOAD(0, 0);
    CP_COMMIT;
    for (int it = 0; it < NCH; it++) {
        if (it + 1 < NCH) {
            QK_LOAD((it + 1) & 1, (it + 1) * 32);
            CP_COMMIT;
            CP_WAIT1;
        } else {
            CP_WAIT0;
        }
        __syncthreads();
        int st = it & 1;
#pragma unroll
        for (int ks = 0; ks < 4; ks++) {
            int k0 = ks * 8;
            unsigned a[4][4], bf[4][2];
#pragma unroll
            for (int mi = 0; mi < 4; mi++) {
                int m = wm + mi * 16 + gid;
                a[mi][0] = AS4(st, m, k0 + tig);
                a[mi][1] = AS4(st, m + 8, k0 + tig);
                a[mi][2] = AS4(st, m, k0 + tig + 4);
                a[mi][3] = AS4(st, m + 8, k0 + tig + 4);
            }
#pragma unroll
            for (int ni = 0; ni < 4; ni++) {
                int n = wn + ni * 8 + gid;
                bf[ni][0] = BS4(st, k0 + tig, n);
                bf[ni][1] = BS4(st, k0 + tig + 4, n);
            }
#pragma unroll
            for (int mi = 0; mi < 4; mi++)
#pragma unroll
                for (int ni = 0; ni < 4; ni++)
                    mma8(acc[mi][ni], a[mi][0], a[mi][1], a[mi][2], a[mi][3],
                         bf[ni][0], bf[ni][1]);
        }
        __syncthreads();
    }

#pragma unroll
    for (int mi = 0; mi < 4; mi++) {
        int o = o_blk + wm + mi * 16 + gid;
        float bv0 = bias[o], bv1 = bias[o + 8];
        float* p0 = out + ((size_t)b * CC + o) * NN + n_blk;
        float* p1 = p0 + (size_t)8 * NN;
#pragma unroll
        for (int ni = 0; ni < 4; ni++) {
            int cb = wn + ni * 8 + tig * 2;
            *(float2*)(p0 + cb) = make_float2(rna(acc[mi][ni][0] + bv0), rna(acc[mi][ni][1] + bv0));
            *(float2*)(p1 + cb) = make_float2(rna(acc[mi][ni][2] + bv1), rna(acc[mi][ni][3] + bv1));
        }
    }
#undef AS4
#undef BS4
}

// ============================================================
// Kernel 5: scores, cp.async double-buffered. S[n][m] = sum_c q[c][n] k[c][m]
// (softmax scale already folded into q)
// ============================================================
__global__ __launch_bounds__(256, 2) void scores_mma_kernel() {
    int b = blockIdx.z;
    int n_blk = blockIdx.y * 128;
    int m_blk = blockIdx.x * 128;

    extern __shared__ unsigned sm[];
    unsigned* Asb = sm;                 // [2][32][136]
    unsigned* Bsb = sm + 2 * 4352;      // [2][32][136]
#define AS5(st, i, j) Asb[(st) * 4352 + (i) * 136 + (j)]
#define BS5(st, i, j) Bsb[(st) * 4352 + (i) * 136 + (j)]

    int tid = threadIdx.x, lane = tid & 31, wid = tid >> 5;
    int gid = lane >> 2, tig = lane & 3;
    int wm = (wid & 1) * 64, wn = (wid >> 1) * 32;
    float acc[4][4][4] = {};

    const float* qp = g_q + (size_t)b * CC * NN;
    const float* kp = g_k + (size_t)b * CC * NN;
    int rb = tid >> 5, c4 = (tid & 31) * 4;

    const int NCH = CC / 32;
#define SC_LOAD(st, c0)                                                               \
    {                                                                                 \
        _Pragma("unroll") for (int r = 0; r < 4; r++) {                               \
            int row = rb + r * 8;                                                     \
            cp16(&AS5(st, row, c4), qp + (size_t)((c0) + row) * NN + n_blk + c4);     \
            cp16(&BS5(st, row, c4), kp + (size_t)((c0) + row) * NN + m_blk + c4);     \
        }                                                                             \
    }

    SC_LOAD(0, 0);
    CP_COMMIT;
    for (int it = 0; it < NCH; it++) {
        if (it + 1 < NCH) {
            SC_LOAD((it + 1) & 1, (it + 1) * 32);
            CP_COMMIT;
            CP_WAIT1;
        } else {
            CP_WAIT0;
        }
        __syncthreads();
        int st = it & 1;
#pragma unroll
        for (int ks = 0; ks < 4; ks++) {
            int k0 = ks * 8;
            unsigned a[4][4], bf[4][2];
#pragma unroll
            for (int mi = 0; mi < 4; mi++) {
                int m = wm + mi * 16 + gid;
                a[mi][0] = AS5(st, k0 + tig, m);
                a[mi][1] = AS5(st, k0 + tig, m + 8);
                a[mi][2] = AS5(st, k0 + tig + 4, m);
                a[mi][3] = AS5(st, k0 + tig + 4, m + 8);
            }
#pragma unroll
            for (int ni = 0; ni < 4; ni++) {
                int n = wn + ni * 8 + gid;
                bf[ni][0] = BS5(st, k0 + tig, n);
                bf[ni][1] = BS5(st, k0 + tig + 4, n);
            }
#pragma unroll
            for (int mi = 0; mi < 4; mi++)
#pragma unroll
                for (int ni = 0; ni < 4; ni++)
                    mma8(acc[mi][ni], a[mi][0], a[mi][1], a[mi][2], a[mi][3],
                         bf[ni][0], bf[ni][1]);
        }
        __syncthreads();
    }

#pragma unroll
    for (int mi = 0; mi < 4; mi++) {
        int rrow = n_blk + wm + mi * 16 + gid;
        float* p0 = g_s + ((size_t)b * NN + rrow) * NN + m_blk;
        float* p1 = p0 + (size_t)8 * NN;
#pragma unroll
        for (int ni = 0; ni < 4; ni++) {
            int cb = wn + ni * 8 + tig * 2;
            *(float2*)(p0 + cb) = make_float2(acc[mi][ni][0], acc[mi][ni][1]);
            *(float2*)(p1 + cb) = make_float2(acc[mi][ni][2], acc[mi][ni][3]);
        }
    }
#undef AS5
#undef BS5
}

// ============================================================
// Kernel 6: row softmax (unchanged except rna on store).
// ============================================================
__global__ void softmax_kernel() {
    int b = blockIdx.y;
    int row = blockIdx.x;
    float* p = g_s + ((size_t)b * NN + row) * NN;
    int tid = threadIdx.x;

    float vals[16];
    float mx = -1e30f;
#pragma unroll
    for (int i = 0; i < 16; i++) {
        vals[i] = p[tid + i * 256];
        mx = fmaxf(mx, vals[i]);
    }
    __shared__ float sred[64];
#pragma unroll
    for (int off = 16; off > 0; off >>= 1)
        mx = fmaxf(mx, __shfl_xor_sync(0xffffffffu, mx, off));
    if ((tid & 31) == 0) sred[tid >> 5] = mx;
    __syncthreads();
    if (tid < 32) {
        float v = (tid < 8) ? sred[tid] : -1e30f;
#pragma unroll
        for (int off = 4; off > 0; off >>= 1)
            v = fmaxf(v, __shfl_xor_sync(0xffffffffu, v, off));
        if (tid == 0) sred[32] = v;
    }
    __syncthreads();
    mx = sred[32];

    float sum = 0.f;
#pragma unroll
    for (int i = 0; i < 16; i++) {
        vals[i] = __expf(vals[i] - mx);
        sum += vals[i];
    }
#pragma unroll
    for (int off = 16; off > 0; off >>= 1)
        sum += __shfl_xor_sync(0xffffffffu, sum, off);
    if ((tid & 31) == 0) sred[tid >> 5] = sum;
    __syncthreads();
    if (tid < 32) {
        float v = (tid < 8) ? sred[tid] : 0.f;
#pragma unroll
        for (int off = 4; off > 0; off >>= 1)
            v += __shfl_xor_sync(0xffffffffu, v, off);
        if (tid == 0) sred[33] = v;
    }
    __syncthreads();
    float inv = 1.f / sred[33];
#pragma unroll
    for (int i = 0; i < 16; i++) p[tid + i * 256] = rna(vals[i] * inv);
}

// ============================================================
// Kernel 7: AV, cp.async double-buffered. att[c][n] = sum_m k[c][m] P[n][m]
// ============================================================
__global__ __launch_bounds__(256, 2) void av_mma_kernel() {
    int b = blockIdx.z;
    int c_blk = blockIdx.y * 128;
    int n_blk = blockIdx.x * 128;

    extern __shared__ unsigned sm[];
    unsigned* Asb = sm;                 // [2][128][36]
    unsigned* Bsb = sm + 2 * 4608;      // [2][128][36]
#define AS7(st, i, j) Asb[(st) * 4608 + (i) * 36 + (j)]
#define BS7(st, i, j) Bsb[(st) * 4608 + (i) * 36 + (j)]

    int tid = threadIdx.x, lane = tid & 31, wid = tid >> 5;
    int gid = lane >> 2, tig = lane & 3;
    int wm = (wid & 1) * 64, wn = (wid >> 1) * 32;
    float acc[4][4][4] = {};

    const float* kp = g_k + (size_t)b * CC * NN;
    const float* pp = g_s + (size_t)b * NN * NN;
    int ra = tid >> 3, m4 = (tid & 7) * 4;

    const int NCH = NN / 32;  // 128
#define AV_LOAD(st, m0)                                                                \
    {                                                                                  \
        _Pragma("unroll") for (int r = 0; r < 4; r++) {                                \
            int row = ra + r * 32;                                                     \
            cp16(&AS7(st, row, m4), kp + (size_t)(c_blk + row) * NN + (m0) + m4);      \
            cp16(&BS7(st, row, m4), pp + (size_t)(n_blk + row) * NN + (m0) + m4);      \
        }                                                                              \
    }

    AV_LOAD(0, 0);
    CP_COMMIT;
    for (int it = 0; it < NCH; it++) {
        if (it + 1 < NCH) {
            AV_LOAD((it + 1) & 1, (it + 1) * 32);
            CP_COMMIT;
            CP_WAIT1;
        } else {
            CP_WAIT0;
        }
        __syncthreads();
        int st = it & 1;
#pragma unroll
        for (int ks = 0; ks < 4; ks++) {
            int k0 = ks * 8;
            unsigned a[4][4], bf[4][2];
#pragma unroll
            for (int mi = 0; mi < 4; mi++) {
                int m = wm + mi * 16 + gid;
                a[mi][0] = AS7(st, m, k0 + tig);
                a[mi][1] = AS7(st, m + 8, k0 + tig);
                a[mi][2] = AS7(st, m, k0 + tig + 4);
                a[mi][3] = AS7(st, m + 8, k0 + tig + 4);
            }
#pragma unroll
            for (int ni = 0; ni < 4; ni++) {
                int n = wn + ni * 8 + gid;
                bf[ni][0] = BS7(st, n, k0 + tig);
                bf[ni][1] = BS7(st, n, k0 + tig + 4);
            }
#pragma unroll
            for (int mi = 0; mi < 4; mi++)
#pragma unroll
                for (int ni = 0; ni < 4; ni++)
                    mma8(acc[mi][ni], a[mi][0], a[mi][1], a[mi][2], a[mi][3],
                         bf[ni][0], bf[ni][1]);
        }
        __syncthreads();
    }

#pragma unroll
    for (int mi = 0; mi < 4; mi++) {
        int c = c_blk + wm + mi * 16 + gid;
        float* p0 = g_att + ((size_t)b * CC + c) * NN + n_blk;
        float* p1 = p0 + (size_t)8 * NN;
#pragma unroll
        for (int ni = 0; ni < 4; ni++) {
            int cb = wn + ni * 8 + tig * 2;
            *(float2*)(p0 + cb) = make_float2(rna(acc[mi][ni][0]), rna(acc[mi][ni][1]));
            *(float2*)(p1 + cb) = make_float2(rna(acc[mi][ni][2]), rna(acc[mi][ni][3]));
        }
    }
#undef AS7
#undef BS7
}

// ============================================================
// Kernel 8: proj + bias + residual, cp.async double-buffered.
// ============================================================
__global__ __launch_bounds__(256, 2) void proj_mma_kernel(
        const float* __restrict__ x, const float* __restrict__ pb,
        float* __restrict__ out) {
    int b = blockIdx.z;
    int o_blk = blockIdx.y * 128, n_blk = blockIdx.x * 128;

    extern __shared__ unsigned sm[];
    unsigned* Asb = sm;                 // [2][128][36]
    unsigned* Bsb = sm + 2 * 128 * 36;  // [2][32][136]
#define AS8(st, i, j) Asb[(st) * 4608 + (i) * 36 + (j)]
#define BS8(st, i, j) Bsb[(st) * 4352 + (i) * 136 + (j)]

    int tid = threadIdx.x, lane = tid & 31, wid = tid >> 5;
    int gid = lane >> 2, tig = lane & 3;
    int wm = (wid & 1) * 64, wn = (wid >> 1) * 32;
    float acc[4][4][4] = {};

    const float* ap = g_att + (size_t)b * CC * NN;
    int rb = tid >> 5, c4 = (tid & 31) * 4;
    int oa = tid >> 3, ca4 = (tid & 7) * 4;

    const int NCH = CC / 32;
#define PJ_LOAD(st, c0)                                                               \
    {                                                                                 \
        _Pragma("unroll") for (int r = 0; r < 4; r++) {                               \
            int o = oa + r * 32;                                                      \
            cp16(&AS8(st, o, ca4), g_pwf + (size_t)(o_blk + o) * CC + (c0) + ca4);    \
        }                                                                             \
        _Pragma("unroll") for (int r = 0; r < 4; r++) {                               \
            int row = rb + r * 8;                                                     \
            cp16(&BS8(st, row, c4), ap + (size_t)((c0) + row) * NN + n_blk + c4);     \
        }                                                                             \
    }

    PJ_LOAD(0, 0);
    CP_COMMIT;
    for (int it = 0; it < NCH; it++) {
        if (it + 1 < NCH) {
            PJ_LOAD((it + 1) & 1, (it + 1) * 32);
            CP_COMMIT;
            CP_WAIT1;
        } else {
            CP_WAIT0;
        }
        __syncthreads();
        int st = it & 1;
#pragma unroll
        for (int ks = 0; ks < 4; ks++) {
            int k0 = ks * 8;
            unsigned a[4][4], bf[4][2];
#pragma unroll
            for (int mi = 0; mi < 4; mi++) {
                int m = wm + mi * 16 + gid;
                a[mi][0] = AS8(st, m, k0 + tig);
                a[mi][1] = AS8(st, m + 8, k0 + tig);
                a[mi][2] = AS8(st, m, k0 + tig + 4);
                a[mi][3] = AS8(st, m + 8, k0 + tig + 4);
            }
#pragma unroll
            for (int ni = 0; ni < 4; ni++) {
                int n = wn + ni * 8 + gid;
                bf[ni][0] = BS8(st, k0 + tig, n);
                bf[ni][1] = BS8(st, k0 + tig + 4, n);
            }
#pragma unroll
            for (int mi = 0; mi < 4; mi++)
#pragma unroll
                for (int ni = 0; ni < 4; ni++)
                    mma8(acc[mi][ni], a[mi][0], a[mi][1], a[mi][2], a[mi][3],
                         bf[ni][0], bf[ni][1]);
        }
        __syncthreads();
    }

#pragma unroll
    for (int mi = 0; mi < 4; mi++) {
        int o = o_blk + wm + mi * 16 + gid;
        float bv0 = pb[o], bv1 = pb[o + 8];
        size_t base0 = ((size_t)b * CC + o) * NN + n_blk;
        size_t base1 = base0 + (size_t)8 * NN;
#pragma unroll
        for (int ni = 0; ni < 4; ni++) {
            int cb = wn + ni * 8 + tig * 2;
            float2 x0 = *(const float2*)(x + base0 + cb);
            float2 x1 = *(const float2*)(x + base1 + cb);
            *(float2*)(out + base0 + cb) =
                make_float2(acc[mi][ni][0] + bv0 + x0.x, acc[mi][ni][1] + bv0 + x0.y);
            *(float2*)(out + base1 + cb) =
                make_float2(acc[mi][ni][2] + bv1 + x1.x, acc[mi][ni][3] + bv1 + x1.y);
        }
    }
#undef AS8
#undef BS8
}

// ============================================================
// launch
// ============================================================
extern "C" void kernel_launch(void* const* d_in, const int* in_sizes, int n_in,
                              void* d_out, int out_size) {
    const float* x     = (const float*)d_in[0];
    const float* gamma = (const float*)d_in[1];
    const float* beta  = (const float*)d_in[2];
    const float* q_w   = (const float*)d_in[3];
    const float* q_b   = (const float*)d_in[4];
    const float* k_w   = (const float*)d_in[5];
    const float* k_b   = (const float*)d_in[6];
    const float* p_w   = (const float*)d_in[7];
    const float* p_b   = (const float*)d_in[8];
    float* out = (float*)d_out;

    (void)in_sizes; (void)n_in; (void)out_size;

    const int SMEM_QK = 2 * (128 * 36 + 32 * 136) * 4;   // 71680
    const int SMEM_SC = 2 * (2 * 32 * 136) * 4;          // 69632
    const int SMEM_AV = 2 * (2 * 128 * 36) * 4;          // 73728
    cudaFuncSetAttribute(qk_mma_kernel, cudaFuncAttributeMaxDynamicSharedMemorySize, SMEM_QK);
    cudaFuncSetAttribute(scores_mma_kernel, cudaFuncAttributeMaxDynamicSharedMemorySize, SMEM_SC);
    cudaFuncSetAttribute(av_mma_kernel, cudaFuncAttributeMaxDynamicSharedMemorySize, SMEM_AV);
    cudaFuncSetAttribute(proj_mma_kernel, cudaFuncAttributeMaxDynamicSharedMemorySize, SMEM_QK);

    gn_stats_kernel<<<dim3(BATCH, GG), 256>>>(x);
    fold_kernel<<<dim3(BATCH, 4), 256>>>(q_w, q_b, k_w, k_b, p_w, gamma, beta);
    xcvt_kernel<<<(BATCH * CC * NN) / 1024, 256>>>(x);

    qk_mma_kernel<<<dim3(NN / 128, CC / 128, BATCH * 2), 256, SMEM_QK>>>();
    scores_mma_kernel<<<dim3(NN / 128, NN / 128, BATCH), 256, SMEM_SC>>>();
    softmax_kernel<<<dim3(NN, BATCH), 256>>>();
    av_mma_kernel<<<dim3(NN / 128, CC / 128, BATCH), 256, SMEM_AV>>>();
    proj_mma_kernel<<<dim3(NN / 128, CC / 128, BATCH), 256, SMEM_QK>>>(x, p_b, out);
}

// round 6
// speedup vs baseline: 5.9440x; 1.5117x over previous
#include <cuda_runtime.h>
#include <cuda_bf16.h>
#include <math.h>
#include <stdint.h>

#define BATCH 8
#define CC 512
#define NN 4096
#define GG 32
#define CPG 16

// ---- scratch (static device globals; allowed by harness rules) ----
__device__ __nv_bfloat16 g_qt[(size_t)BATCH * NN * CC];   // q_t [b][n][c] bf16
__device__ __nv_bfloat16 g_ktb[(size_t)BATCH * NN * CC];  // k_t [b][m][c] bf16
__device__ __nv_bfloat16 g_kb[(size_t)BATCH * CC * NN];   // k   [b][c][m] bf16
__device__ __nv_bfloat16 g_s[(size_t)BATCH * NN * NN];    // scores/probs bf16
__device__ float g_att[(size_t)BATCH * CC * NN];          // rna(x) then att [c][n] fp32
__device__ float g_stats[BATCH * GG * 2];
__device__ float g_qwf[(size_t)BATCH * CC * CC];
__device__ float g_kwf[(size_t)BATCH * CC * CC];
__device__ float g_pwf[(size_t)CC * CC];
__device__ float g_qbf[BATCH * CC];
__device__ float g_kbf[BATCH * CC];

// ============================================================
// helpers
// ============================================================
__device__ __forceinline__ unsigned f2tf(float f) {
    unsigned u;
    asm("cvt.rna.tf32.f32 %0, %1;" : "=r"(u) : "f"(f));
    return u;
}
__device__ __forceinline__ float rna(float f) { return __uint_as_float(f2tf(f)); }

__device__ __forceinline__ unsigned packbf(float x, float y) {
    __nv_bfloat162 h = __float22bfloat162_rn(make_float2(x, y));
    return *reinterpret_cast<unsigned*>(&h);
}

__device__ __forceinline__ void mma8(float* c, unsigned a0, unsigned a1, unsigned a2, unsigned a3,
                                     unsigned b0, unsigned b1) {
    asm volatile(
        "mma.sync.aligned.m16n8k8.row.col.f32.tf32.tf32.f32 "
        "{%0,%1,%2,%3},{%4,%5,%6,%7},{%8,%9},{%0,%1,%2,%3};"
        : "+f"(c[0]), "+f"(c[1]), "+f"(c[2]), "+f"(c[3])
        : "r"(a0), "r"(a1), "r"(a2), "r"(a3), "r"(b0), "r"(b1));
}

__device__ __forceinline__ void mma16(float* c, unsigned a0, unsigned a1, unsigned a2, unsigned a3,
                                      unsigned b0, unsigned b1) {
    asm volatile(
        "mma.sync.aligned.m16n8k16.row.col.f32.bf16.bf16.f32 "
        "{%0,%1,%2,%3},{%4,%5,%6,%7},{%8,%9},{%0,%1,%2,%3};"
        : "+f"(c[0]), "+f"(c[1]), "+f"(c[2]), "+f"(c[3])
        : "r"(a0), "r"(a1), "r"(a2), "r"(a3), "r"(b0), "r"(b1));
}

__device__ __forceinline__ void cp16(void* smem_dst, const void* gsrc) {
    unsigned s = (unsigned)__cvta_generic_to_shared(smem_dst);
    asm volatile("cp.async.cg.shared.global [%0], [%1], 16;" :: "r"(s), "l"(gsrc));
}
#define CP_COMMIT asm volatile("cp.async.commit_group;")
#define CP_WAIT1 asm volatile("cp.async.wait_group 1;")
#define CP_WAIT0 asm volatile("cp.async.wait_group 0;")

// ============================================================
// Kernel 1: GroupNorm statistics
// ============================================================
__global__ void gn_stats_kernel(const float* __restrict__ x) {
    int b = blockIdx.x, g = blockIdx.y;
    const float* xp = x + ((size_t)(b * CC) + g * CPG) * NN;
    float s = 0.f, s2 = 0.f;
    for (int i = threadIdx.x; i < CPG * NN; i += 256) {
        float v = xp[i];
        s += v;
        s2 += v * v;
    }
    __shared__ float sh[256], sh2[256];
    sh[threadIdx.x] = s;
    sh2[threadIdx.x] = s2;
    __syncthreads();
    for (int off = 128; off > 0; off >>= 1) {
        if (threadIdx.x < off) {
            sh[threadIdx.x] += sh[threadIdx.x + off];
            sh2[threadIdx.x] += sh2[threadIdx.x + off];
        }
        __syncthreads();
    }
    if (threadIdx.x == 0) {
        const float inv = 1.f / (float)(CPG * NN);
        float mu = sh[0] * inv;
        float var = sh2[0] * inv - mu * mu;
        g_stats[(b * GG + g) * 2 + 0] = mu;
        g_stats[(b * GG + g) * 2 + 1] = rsqrtf(var + 1e-6f);
    }
}

// ============================================================
// Kernel 2: fold GN + softmax scale into weights/biases (rna)
// ============================================================
__global__ void fold_kernel(const float* __restrict__ qw, const float* __restrict__ qb,
                            const float* __restrict__ kw, const float* __restrict__ kb,
                            const float* __restrict__ pw,
                            const float* __restrict__ gamma, const float* __restrict__ beta) {
    int b = blockIdx.x, o0 = blockIdx.y * 128;
    __shared__ float ga[CC], be[CC];
    for (int c = threadIdx.x; c < CC; c += 256) {
        int g = c >> 4;
        float mu = g_stats[(b * GG + g) * 2 + 0];
        float rstd = g_stats[(b * GG + g) * 2 + 1];
        float gg = gamma[c] * rstd;
        ga[c] = gg;
        be[c] = beta[c] - mu * gg;
    }
    __syncthreads();
    const float s = rsqrtf((float)CC);
    for (int idx = threadIdx.x; idx < 128 * CC; idx += 256) {
        int o = o0 + (idx >> 9), c = idx & (CC - 1);
        g_qwf[((size_t)b * CC + o) * CC + c] = rna(qw[(size_t)o * CC + c] * ga[c] * s);
        g_kwf[((size_t)b * CC + o) * CC + c] = rna(kw[(size_t)o * CC + c] * ga[c]);
    }
    {
        int o = o0 + (threadIdx.x >> 1);
        int h = (threadIdx.x & 1) * 256;
        float sq = 0.f, sk = 0.f;
        for (int c = h; c < h + 256; c++) {
            sq += qw[(size_t)o * CC + c] * be[c];
            sk += kw[(size_t)o * CC + c] * be[c];
        }
        sq += __shfl_xor_sync(0xffffffffu, sq, 1);
        sk += __shfl_xor_sync(0xffffffffu, sk, 1);
        if ((threadIdx.x & 1) == 0) {
            g_qbf[b * CC + o] = (qb[o] + sq) * s;
            g_kbf[b * CC + o] = kb[o] + sk;
        }
    }
    if (b == 0) {
        for (int idx = threadIdx.x; idx < 128 * CC; idx += 256) {
            int o = o0 + (idx >> 9), c = idx & (CC - 1);
            g_pwf[(size_t)o * CC + c] = rna(pw[(size_t)o * CC + c]);
        }
    }
}

// ============================================================
// Kernel 3: rna(x) -> g_att (B operand of qk GEMM)
// ============================================================
__global__ void xcvt_kernel(const float* __restrict__ x) {
    size_t i = ((size_t)blockIdx.x * 256 + threadIdx.x) * 4;
    float4 v = *(const float4*)(x + i);
    uint4 t = make_uint4(f2tf(v.x), f2tf(v.y), f2tf(v.z), f2tf(v.w));
    *(uint4*)&g_att[i] = t;
}

// ============================================================
// Kernel 4: q/k projection (tf32) + bf16 transposed epilogues.
//   D[o 128][n 128] = W'[o][c] · xr[c][n]
//   which=0 -> q_t bf16 [n][c];  which=1 -> k bf16 [c][m] AND k_t bf16 [m][c]
// ============================================================
__global__ __launch_bounds__(256, 2) void qk_mma_kernel() {
    int b = blockIdx.z >> 1, which = blockIdx.z & 1;
    const float* w = (which ? g_kwf : g_qwf) + (size_t)b * CC * CC;
    const float* bias = (which ? g_kbf : g_qbf) + b * CC;
    int o_blk = blockIdx.y * 128, n_blk = blockIdx.x * 128;

    extern __shared__ unsigned sm[];
    unsigned* Asb = sm;                 // [2][128][36]
    unsigned* Bsb = sm + 2 * 128 * 36;  // [2][32][136]
#define AS4(st, i, j) Asb[(st) * 4608 + (i) * 36 + (j)]
#define BS4(st, i, j) Bsb[(st) * 4352 + (i) * 136 + (j)]

    int tid = threadIdx.x, lane = tid & 31, wid = tid >> 5;
    int gid = lane >> 2, tig = lane & 3;
    int wm = (wid & 1) * 64, wn = (wid >> 1) * 32;
    float acc[4][4][4] = {};

    const float* xb = g_att + (size_t)b * CC * NN;
    int rb = tid >> 5, c4 = (tid & 31) * 4;
    int oa = tid >> 3, ca4 = (tid & 7) * 4;

    const int NCH = CC / 32;  // 16
#define QK_LOAD(st, c0)                                                              \
    {                                                                                \
        _Pragma("unroll") for (int r = 0; r < 4; r++) {                              \
            int o = oa + r * 32;                                                     \
            cp16(&AS4(st, o, ca4), w + (size_t)(o_blk + o) * CC + (c0) + ca4);       \
        }                                                                            \
        _Pragma("unroll") for (int r = 0; r < 4; r++) {                              \
            int row = rb + r * 8;                                                    \
            cp16(&BS4(st, row, c4), xb + (size_t)((c0) + row) * NN + n_blk + c4);    \
        }                                                                            \
    }

    QK_LOAD(0, 0);
    CP_COMMIT;
    for (int it = 0; it < NCH; it++) {
        if (it + 1 < NCH) {
            QK_LOAD((it + 1) & 1, (it + 1) * 32);
            CP_COMMIT;
            CP_WAIT1;
        } else {
            CP_WAIT0;
        }
        __syncthreads();
        int st = it & 1;
#pragma unroll
        for (int ks = 0; ks < 4; ks++) {
            int k0 = ks * 8;
            unsigned a[4][4], bf[4][2];
#pragma unroll
            for (int mi = 0; mi < 4; mi++) {
                int m = wm + mi * 16 + gid;
                a[mi][0] = AS4(st, m, k0 + tig);
                a[mi][1] = AS4(st, m + 8, k0 + tig);
                a[mi][2] = AS4(st, m, k0 + tig + 4);
                a[mi][3] = AS4(st, m + 8, k0 + tig + 4);
            }
#pragma unroll
            for (int ni = 0; ni < 4; ni++) {
                int n = wn + ni * 8 + gid;
                bf[ni][0] = BS4(st, k0 + tig, n);
                bf[ni][1] = BS4(st, k0 + tig + 4, n);
            }
#pragma unroll
            for (int mi = 0; mi < 4; mi++)
#pragma unroll
                for (int ni = 0; ni < 4; ni++)
                    mma8(acc[mi][ni], a[mi][0], a[mi][1], a[mi][2], a[mi][3],
                         bf[ni][0], bf[ni][1]);
        }
        __syncthreads();
    }

    // ---- epilogue: bias, bf16, transpose via smem (stage smem now dead) ----
    __nv_bfloat16* T = (__nv_bfloat16*)sm;  // [128 n][136 o-pitch]
#pragma unroll
    for (int mi = 0; mi < 4; mi++) {
        int ol = wm + mi * 16 + gid;
        float bv0 = bias[o_blk + ol], bv1 = bias[o_blk + ol + 8];
#pragma unroll
        for (int ni = 0; ni < 4; ni++) {
            int nl = wn + ni * 8 + tig * 2;
            float v00 = acc[mi][ni][0] + bv0, v01 = acc[mi][ni][1] + bv0;
            float v10 = acc[mi][ni][2] + bv1, v11 = acc[mi][ni][3] + bv1;
            __nv_bfloat16 b00 = __float2bfloat16_rn(v00), b01 = __float2bfloat16_rn(v01);
            __nv_bfloat16 b10 = __float2bfloat16_rn(v10), b11 = __float2bfloat16_rn(v11);
            if (which) {
                // k[c][m] direct bf16 pairs
                __nv_bfloat162 p0; p0.x = b00; p0.y = b01;
                __nv_bfloat162 p1; p1.x = b10; p1.y = b11;
                *(__nv_bfloat162*)&g_kb[((size_t)b * CC + o_blk + ol) * NN + n_blk + nl] = p0;
                *(__nv_bfloat162*)&g_kb[((size_t)b * CC + o_blk + ol + 8) * NN + n_blk + nl] = p1;
            }
            T[nl * 136 + ol] = b00;
            T[(nl + 1) * 136 + ol] = b01;
            T[nl * 136 + ol + 8] = b10;
            T[(nl + 1) * 136 + ol + 8] = b11;
        }
    }
    __syncthreads();
    {
        __nv_bfloat16* dst = (which ? g_ktb : g_qt) + (size_t)b * NN * CC;
        int nl = tid >> 1, h = tid & 1;
        __nv_bfloat16* drow = dst + (size_t)(n_blk + nl) * CC + o_blk + h * 64;
        const __nv_bfloat16* srow = T + nl * 136 + h * 64;
#pragma unroll
        for (int j = 0; j < 8; j++)
            *(uint4*)(drow + j * 8) = *(const uint4*)(srow + j * 8);
    }
#undef AS4
#undef BS4
}

// ============================================================
// Kernel 5: scores (bf16 m16n8k16). S[n][m] = sum_c q_t[n][c] * k_t[m][c]
// K-chunk 64 bf16 = 32 uint pairs; smem pitch 36 uint.
// ============================================================
__global__ __launch_bounds__(256, 2) void scores_bf_kernel() {
    int b = blockIdx.z;
    int nB = blockIdx.y * 128, mB = blockIdx.x * 128;

    extern __shared__ unsigned smu[];  // stage s: A at s*9216, B at s*9216+4608

    int tid = threadIdx.x, lane = tid & 31, wid = tid >> 5;
    int gid = lane >> 2, tig = lane & 3;
    int wm = (wid & 1) * 64, wn = (wid >> 1) * 32;
    float acc[4][4][4] = {};

    const __nv_bfloat16* qp = g_qt + (size_t)b * NN * CC + (size_t)nB * CC;
    const __nv_bfloat16* kp = g_ktb + (size_t)b * NN * CC + (size_t)mB * CC;
    int row = tid >> 3, seg = tid & 7;

    const int NCH = CC / 64;  // 8
#define SC_LOAD(st, c0)                                                               \
    {                                                                                 \
        _Pragma("unroll") for (int r = 0; r < 4; r++) {                               \
            int rr = row + r * 32;                                                    \
            cp16(&smu[(st) * 9216 + rr * 36 + seg * 4], qp + (size_t)rr * CC + (c0) + seg * 8); \
            cp16(&smu[(st) * 9216 + 4608 + rr * 36 + seg * 4], kp + (size_t)rr * CC + (c0) + seg * 8); \
        }                                                                             \
    }

    SC_LOAD(0, 0);
    CP_COMMIT;
    for (int it = 0; it < NCH; it++) {
        if (it + 1 < NCH) {
            SC_LOAD((it + 1) & 1, (it + 1) * 64);
            CP_COMMIT;
            CP_WAIT1;
        } else {
            CP_WAIT0;
        }
        __syncthreads();
        const unsigned* A = smu + (it & 1) * 9216;
        const unsigned* B = A + 4608;
#pragma unroll
        for (int ks = 0; ks < 4; ks++) {
            int k0 = ks * 8;
            unsigned a[4][4], bf[4][2];
#pragma unroll
            for (int mi = 0; mi < 4; mi++) {
                int m = wm + mi * 16 + gid;
                a[mi][0] = A[m * 36 + k0 + tig];
                a[mi][1] = A[(m + 8) * 36 + k0 + tig];
                a[mi][2] = A[m * 36 + k0 + tig + 4];
                a[mi][3] = A[(m + 8) * 36 + k0 + tig + 4];
            }
#pragma unroll
            for (int ni = 0; ni < 4; ni++) {
                int n = wn + ni * 8 + gid;
                bf[ni][0] = B[n * 36 + k0 + tig];
                bf[ni][1] = B[n * 36 + k0 + tig + 4];
            }
#pragma unroll
            for (int mi = 0; mi < 4; mi++)
#pragma unroll
                for (int ni = 0; ni < 4; ni++)
                    mma16(acc[mi][ni], a[mi][0], a[mi][1], a[mi][2], a[mi][3],
                          bf[ni][0], bf[ni][1]);
        }
        __syncthreads();
    }

#pragma unroll
    for (int mi = 0; mi < 4; mi++) {
        int qrow = nB + wm + mi * 16 + gid;
        __nv_bfloat16* p0 = g_s + ((size_t)b * NN + qrow) * NN + mB;
        __nv_bfloat16* p1 = p0 + (size_t)8 * NN;
#pragma unroll
        for (int ni = 0; ni < 4; ni++) {
            int cb = wn + ni * 8 + tig * 2;
            *(unsigned*)(p0 + cb) = packbf(acc[mi][ni][0], acc[mi][ni][1]);
            *(unsigned*)(p1 + cb) = packbf(acc[mi][ni][2], acc[mi][ni][3]);
        }
    }
}

// ============================================================
// Kernel 6: row softmax over m, bf16 in/out, fp32 math.
// ============================================================
__global__ void softmax_kernel() {
    int b = blockIdx.y;
    int row = blockIdx.x;
    unsigned* p = (unsigned*)(g_s + ((size_t)b * NN + row) * NN);  // 2048 uints
    int tid = threadIdx.x;

    float vals[16];
    float mx = -1e30f;
#pragma unroll
    for (int i = 0; i < 8; i++) {
        unsigned u = p[tid + i * 256];
        __nv_bfloat162 h = *reinterpret_cast<__nv_bfloat162*>(&u);
        float2 f = __bfloat1622float2(h);
        vals[2 * i] = f.x;
        vals[2 * i + 1] = f.y;
        mx = fmaxf(mx, fmaxf(f.x, f.y));
    }
    __shared__ float sred[64];
#pragma unroll
    for (int off = 16; off > 0; off >>= 1)
        mx = fmaxf(mx, __shfl_xor_sync(0xffffffffu, mx, off));
    if ((tid & 31) == 0) sred[tid >> 5] = mx;
    __syncthreads();
    if (tid < 32) {
        float v = (tid < 8) ? sred[tid] : -1e30f;
#pragma unroll
        for (int off = 4; off > 0; off >>= 1)
            v = fmaxf(v, __shfl_xor_sync(0xffffffffu, v, off));
        if (tid == 0) sred[32] = v;
    }
    __syncthreads();
    mx = sred[32];

    float sum = 0.f;
#pragma unroll
    for (int i = 0; i < 16; i++) {
        vals[i] = __expf(vals[i] - mx);
        sum += vals[i];
    }
#pragma unroll
    for (int off = 16; off > 0; off >>= 1)
        sum += __shfl_xor_sync(0xffffffffu, sum, off);
    if ((tid & 31) == 0) sred[tid >> 5] = sum;
    __syncthreads();
    if (tid < 32) {
        float v = (tid < 8) ? sred[tid] : 0.f;
#pragma unroll
        for (int off = 4; off > 0; off >>= 1)
            v += __shfl_xor_sync(0xffffffffu, v, off);
        if (tid == 0) sred[33] = v;
    }
    __syncthreads();
    float inv = 1.f / sred[33];
#pragma unroll
    for (int i = 0; i < 8; i++)
        p[tid + i * 256] = packbf(vals[2 * i] * inv, vals[2 * i + 1] * inv);
}

// ============================================================
// Kernel 7: AV (bf16 m16n8k16). att[c][n] = sum_m k[c][m] * P[n][m]
// Output fp32 rna [c][n] for tf32 proj.
// ============================================================
__global__ __launch_bounds__(256, 2) void av_bf_kernel() {
    int b = blockIdx.z;
    int cB = blockIdx.y * 128, nB = blockIdx.x * 128;

    extern __shared__ unsigned smu[];

    int tid = threadIdx.x, lane = tid & 31, wid = tid >> 5;
    int gid = lane >> 2, tig = lane & 3;
    int wm = (wid & 1) * 64, wn = (wid >> 1) * 32;
    float acc[4][4][4] = {};

    const __nv_bfloat16* kp = g_kb + (size_t)b * CC * NN + (size_t)cB * NN;
    const __nv_bfloat16* pp = g_s + (size_t)b * NN * NN + (size_t)nB * NN;
    int row = tid >> 3, seg = tid & 7;

    const int NCH = NN / 64;  // 64
#define AV_LOAD(st, m0)                                                               \
    {                                                                                 \
        _Pragma("unroll") for (int r = 0; r < 4; r++) {                               \
            int rr = row + r * 32;                                                    \
            cp16(&smu[(st) * 9216 + rr * 36 + seg * 4], kp + (size_t)rr * NN + (m0) + seg * 8); \
            cp16(&smu[(st) * 9216 + 4608 + rr * 36 + seg * 4], pp + (size_t)rr * NN + (m0) + seg * 8); \
        }                                                                             \
    }

    AV_LOAD(0, 0);
    CP_COMMIT;
    for (int it = 0; it < NCH; it++) {
        if (it + 1 < NCH) {
            AV_LOAD((it + 1) & 1, (it + 1) * 64);
            CP_COMMIT;
            CP_WAIT1;
        } else {
            CP_WAIT0;
        }
        __syncthreads();
        const unsigned* A = smu + (it & 1) * 9216;
        const unsigned* B = A + 4608;
#pragma unroll
        for (int ks = 0; ks < 4; ks++) {
            int k0 = ks * 8;
            unsigned a[4][4], bf[4][2];
#pragma unroll
            for (int mi = 0; mi < 4; mi++) {
                int m = wm + mi * 16 + gid;
                a[mi][0] = A[m * 36 + k0 + tig];
                a[mi][1] = A[(m + 8) * 36 + k0 + tig];
                a[mi][2] = A[m * 36 + k0 + tig + 4];
                a[mi][3] = A[(m + 8) * 36 + k0 + tig + 4];
            }
#pragma unroll
            for (int ni = 0; ni < 4; ni++) {
                int n = wn + ni * 8 + gid;
                bf[ni][0] = B[n * 36 + k0 + tig];
                bf[ni][1] = B[n * 36 + k0 + tig + 4];
            }
#pragma unroll
            for (int mi = 0; mi < 4; mi++)
#pragma unroll
                for (int ni = 0; ni < 4; ni++)
                    mma16(acc[mi][ni], a[mi][0], a[mi][1], a[mi][2], a[mi][3],
                          bf[ni][0], bf[ni][1]);
        }
        __syncthreads();
    }

#pragma unroll
    for (int mi = 0; mi < 4; mi++) {
        int c = cB + wm + mi * 16 + gid;
        float* p0 = g_att + ((size_t)b * CC + c) * NN + nB;
        float* p1 = p0 + (size_t)8 * NN;
#pragma unroll
        for (int ni = 0; ni < 4; ni++) {
            int cb = wn + ni * 8 + tig * 2;
            *(float2*)(p0 + cb) = make_float2(rna(acc[mi][ni][0]), rna(acc[mi][ni][1]));
            *(float2*)(p1 + cb) = make_float2(rna(acc[mi][ni][2]), rna(acc[mi][ni][3]));
        }
    }
}

// ============================================================
// Kernel 8: proj + bias + residual (tf32, unchanged from R3)
// ============================================================
__global__ __launch_bounds__(256, 2) void proj_mma_kernel(
        const float* __restrict__ x, const float* __restrict__ pb,
        float* __restrict__ out) {
    int b = blockIdx.z;
    int o_blk = blockIdx.y * 128, n_blk = blockIdx.x * 128;

    extern __shared__ unsigned sm[];
    unsigned* Asb = sm;                 // [2][128][36]
    unsigned* Bsb = sm + 2 * 128 * 36;  // [2][32][136]
#define AS8(st, i, j) Asb[(st) * 4608 + (i) * 36 + (j)]
#define BS8(st, i, j) Bsb[(st) * 4352 + (i) * 136 + (j)]

    int tid = threadIdx.x, lane = tid & 31, wid = tid >> 5;
    int gid = lane >> 2, tig = lane & 3;
    int wm = (wid & 1) * 64, wn = (wid >> 1) * 32;
    float acc[4][4][4] = {};

    const float* ap = g_att + (size_t)b * CC * NN;
    int rb = tid >> 5, c4 = (tid & 31) * 4;
    int oa = tid >> 3, ca4 = (tid & 7) * 4;

    const int NCH = CC / 32;
#define PJ_LOAD(st, c0)                                                               \
    {                                                                                 \
        _Pragma("unroll") for (int r = 0; r < 4; r++) {                               \
            int o = oa + r * 32;                                                      \
            cp16(&AS8(st, o, ca4), g_pwf + (size_t)(o_blk + o) * CC + (c0) + ca4);    \
        }                                                                             \
        _Pragma("unroll") for (int r = 0; r < 4; r++) {                               \
            int row = rb + r * 8;                                                     \
            cp16(&BS8(st, row, c4), ap + (size_t)((c0) + row) * NN + n_blk + c4);     \
        }                                                                             \
    }

    PJ_LOAD(0, 0);
    CP_COMMIT;
    for (int it = 0; it < NCH; it++) {
        if (it + 1 < NCH) {
            PJ_LOAD((it + 1) & 1, (it + 1) * 32);
            CP_COMMIT;
            CP_WAIT1;
        } else {
            CP_WAIT0;
        }
        __syncthreads();
        int st = it & 1;
#pragma unroll
        for (int ks = 0; ks < 4; ks++) {
            int k0 = ks * 8;
            unsigned a[4][4], bf[4][2];
#pragma unroll
            for (int mi = 0; mi < 4; mi++) {
                int m = wm + mi * 16 + gid;
                a[mi][0] = AS8(st, m, k0 + tig);
                a[mi][1] = AS8(st, m + 8, k0 + tig);
                a[mi][2] = AS8(st, m, k0 + tig + 4);
                a[mi][3] = AS8(st, m + 8, k0 + tig + 4);
            }
#pragma unroll
            for (int ni = 0; ni < 4; ni++) {
                int n = wn + ni * 8 + gid;
                bf[ni][0] = BS8(st, k0 + tig, n);
                bf[ni][1] = BS8(st, k0 + tig + 4, n);
            }
#pragma unroll
            for (int mi = 0; mi < 4; mi++)
#pragma unroll
                for (int ni = 0; ni < 4; ni++)
                    mma8(acc[mi][ni], a[mi][0], a[mi][1], a[mi][2], a[mi][3],
                         bf[ni][0], bf[ni][1]);
        }
        __syncthreads();
    }

#pragma unroll
    for (int mi = 0; mi < 4; mi++) {
        int o = o_blk + wm + mi * 16 + gid;
        float bv0 = pb[o], bv1 = pb[o + 8];
        size_t base0 = ((size_t)b * CC + o) * NN + n_blk;
        size_t base1 = base0 + (size_t)8 * NN;
#pragma unroll
        for (int ni = 0; ni < 4; ni++) {
            int cb = wn + ni * 8 + tig * 2;
            float2 x0 = *(const float2*)(x + base0 + cb);
            float2 x1 = *(const float2*)(x + base1 + cb);
            *(float2*)(out + base0 + cb) =
                make_float2(acc[mi][ni][0] + bv0 + x0.x, acc[mi][ni][1] + bv0 + x0.y);
            *(float2*)(out + base1 + cb) =
                make_float2(acc[mi][ni][2] + bv1 + x1.x, acc[mi][ni][3] + bv1 + x1.y);
        }
    }
#undef AS8
#undef BS8
}

// ============================================================
// launch
// ============================================================
extern "C" void kernel_launch(void* const* d_in, const int* in_sizes, int n_in,
                              void* d_out, int out_size) {
    const float* x     = (const float*)d_in[0];
    const float* gamma = (const float*)d_in[1];
    const float* beta  = (const float*)d_in[2];
    const float* q_w   = (const float*)d_in[3];
    const float* q_b   = (const float*)d_in[4];
    const float* k_w   = (const float*)d_in[5];
    const float* k_b   = (const float*)d_in[6];
    const float* p_w   = (const float*)d_in[7];
    const float* p_b   = (const float*)d_in[8];
    float* out = (float*)d_out;

    (void)in_sizes; (void)n_in; (void)out_size;

    const int SMEM_QK = 2 * (128 * 36 + 32 * 136) * 4;   // 71680
    const int SMEM_BF = 2 * 9216 * 4;                    // 73728
    cudaFuncSetAttribute(qk_mma_kernel, cudaFuncAttributeMaxDynamicSharedMemorySize, SMEM_QK);
    cudaFuncSetAttribute(scores_bf_kernel, cudaFuncAttributeMaxDynamicSharedMemorySize, SMEM_BF);
    cudaFuncSetAttribute(av_bf_kernel, cudaFuncAttributeMaxDynamicSharedMemorySize, SMEM_BF);
    cudaFuncSetAttribute(proj_mma_kernel, cudaFuncAttributeMaxDynamicSharedMemorySize, SMEM_QK);

    gn_stats_kernel<<<dim3(BATCH, GG), 256>>>(x);
    fold_kernel<<<dim3(BATCH, 4), 256>>>(q_w, q_b, k_w, k_b, p_w, gamma, beta);
    xcvt_kernel<<<(BATCH * CC * NN) / 1024, 256>>>(x);

    qk_mma_kernel<<<dim3(NN / 128, CC / 128, BATCH * 2), 256, SMEM_QK>>>();
    scores_bf_kernel<<<dim3(NN / 128, NN / 128, BATCH), 256, SMEM_BF>>>();
    softmax_kernel<<<dim3(NN, BATCH), 256>>>();
    av_bf_kernel<<<dim3(NN / 128, CC / 128, BATCH), 256, SMEM_BF>>>();
    proj_mma_kernel<<<dim3(NN / 128, CC / 128, BATCH), 256, SMEM_QK>>>(x, p_b, out);
}

// round 7
// speedup vs baseline: 7.0400x; 1.1844x over previous
#include <cuda_runtime.h>
#include <cuda_bf16.h>
#include <math.h>
#include <stdint.h>

#define BATCH 8
#define CC 512
#define NN 4096
#define GG 32
#define CPG 16

// ---- scratch (static device globals; allowed by harness rules) ----
__device__ __nv_bfloat16 g_qt[(size_t)BATCH * NN * CC];    // q_t  [b][n][c]
__device__ __nv_bfloat16 g_ktb[(size_t)BATCH * NN * CC];   // k_t  [b][m][c]
__device__ __nv_bfloat16 g_kb[(size_t)BATCH * CC * NN];    // k    [b][c][m]
__device__ __nv_bfloat16 g_xt[(size_t)BATCH * NN * CC];    // x_t  [b][n][c]
__device__ __nv_bfloat16 g_attt[(size_t)BATCH * NN * CC];  // att_t[b][n][c]
__device__ __nv_bfloat16 g_s[(size_t)BATCH * NN * NN];     // scores/probs [b][n][m]
__device__ __nv_bfloat16 g_qwf[(size_t)BATCH * CC * CC];   // folded q weights
__device__ __nv_bfloat16 g_kwf[(size_t)BATCH * CC * CC];   // folded k weights
__device__ __nv_bfloat16 g_pwf[(size_t)CC * CC];           // proj weights bf16
__device__ float g_stats[BATCH * GG * 2];
__device__ float g_qbf[BATCH * CC];
__device__ float g_kbf[BATCH * CC];

// ============================================================
// helpers
// ============================================================
__device__ __forceinline__ unsigned packbf(float x, float y) {
    __nv_bfloat162 h = __float22bfloat162_rn(make_float2(x, y));
    return *reinterpret_cast<unsigned*>(&h);
}

__device__ __forceinline__ void mma16(float* c, unsigned a0, unsigned a1, unsigned a2, unsigned a3,
                                      unsigned b0, unsigned b1) {
    asm volatile(
        "mma.sync.aligned.m16n8k16.row.col.f32.bf16.bf16.f32 "
        "{%0,%1,%2,%3},{%4,%5,%6,%7},{%8,%9},{%0,%1,%2,%3};"
        : "+f"(c[0]), "+f"(c[1]), "+f"(c[2]), "+f"(c[3])
        : "r"(a0), "r"(a1), "r"(a2), "r"(a3), "r"(b0), "r"(b1));
}

#define LDSM4(r0, r1, r2, r3, addr) \
    asm volatile("ldmatrix.sync.aligned.m8n8.x4.shared.b16 {%0,%1,%2,%3}, [%4];" \
                 : "=r"(r0), "=r"(r1), "=r"(r2), "=r"(r3) : "r"(addr))

__device__ __forceinline__ void cp16(void* smem_dst, const void* gsrc) {
    unsigned s = (unsigned)__cvta_generic_to_shared(smem_dst);
    asm volatile("cp.async.cg.shared.global [%0], [%1], 16;" :: "r"(s), "l"(gsrc));
}
#define CP_COMMIT asm volatile("cp.async.commit_group;")
#define CP_WAIT1 asm volatile("cp.async.wait_group 1;")
#define CP_WAIT0 asm volatile("cp.async.wait_group 0;")

__device__ __forceinline__ uint32_t smem_u32(const void* p) {
    uint32_t a;
    asm("{ .reg .u64 t; cvta.to.shared.u64 t, %1; cvt.u32.u64 %0, t; }" : "=r"(a) : "l"(p));
    return a;
}

// ============================================================
// Unified bf16 GEMM mainloop.
//   acc[mi][ni][] += A[128 rows m][k] · B[128 rows n][k]^T  over K = NCH*64
// Operands MK-major bf16 (k contiguous), ld in elements.
// smem: stage s at s*36864: A tile [128][72 bf16] then B tile at +18432.
// ============================================================
#define STAGE_B 36864
#define SMEM_DYN (2 * STAGE_B)

__device__ __forceinline__ void bf_gemm(const __nv_bfloat16* A, size_t ldA,
                                        const __nv_bfloat16* B, size_t ldB,
                                        int NCH, char* sdyn, uint32_t sbase,
                                        float acc[4][4][4]) {
    int tid = threadIdx.x, lane = tid & 31, wid = tid >> 5;
    int wm = (wid & 1) * 64, wn = (wid >> 1) * 32;
    int lrow = tid >> 3, lseg = tid & 7;

    // ldmatrix lane-address offsets (bytes)
    uint32_t a_off = (uint32_t)(((lane & 7) + ((lane >> 3) & 1) * 8) * 144 + (lane >> 4) * 16);
    uint32_t b_off = (uint32_t)((((lane >> 4) << 3) + (lane & 7)) * 144 + ((lane >> 3) & 1) * 16);

#define BF_LOAD(st, c0)                                                                   \
    {                                                                                     \
        _Pragma("unroll") for (int r = 0; r < 4; r++) {                                   \
            int rr = lrow + r * 32;                                                       \
            cp16(sdyn + (st) * STAGE_B + rr * 144 + lseg * 16,                            \
                 A + (size_t)rr * ldA + (c0) + lseg * 8);                                 \
            cp16(sdyn + (st) * STAGE_B + 18432 + rr * 144 + lseg * 16,                    \
                 B + (size_t)rr * ldB + (c0) + lseg * 8);                                 \
        }                                                                                 \
    }

    BF_LOAD(0, 0);
    CP_COMMIT;
    for (int it = 0; it < NCH; it++) {
        if (it + 1 < NCH) {
            BF_LOAD((it + 1) & 1, (it + 1) * 64);
            CP_COMMIT;
            CP_WAIT1;
        } else {
            CP_WAIT0;
        }
        __syncthreads();
        uint32_t sA = sbase + (it & 1) * STAGE_B + wm * 144;
        uint32_t sB = sbase + (it & 1) * STAGE_B + 18432 + wn * 144;
#pragma unroll
        for (int ks = 0; ks < 4; ks++) {
            unsigned a[4][4], bb[2][4];
#pragma unroll
            for (int mi = 0; mi < 4; mi++)
                LDSM4(a[mi][0], a[mi][1], a[mi][2], a[mi][3],
                      sA + mi * (16 * 144) + ks * 32 + a_off);
#pragma unroll
            for (int np = 0; np < 2; np++)
                LDSM4(bb[np][0], bb[np][1], bb[np][2], bb[np][3],
                      sB + np * (16 * 144) + ks * 32 + b_off);
#pragma unroll
            for (int mi = 0; mi < 4; mi++) {
                mma16(acc[mi][0], a[mi][0], a[mi][1], a[mi][2], a[mi][3], bb[0][0], bb[0][1]);
                mma16(acc[mi][1], a[mi][0], a[mi][1], a[mi][2], a[mi][3], bb[0][2], bb[0][3]);
                mma16(acc[mi][2], a[mi][0], a[mi][1], a[mi][2], a[mi][3], bb[1][0], bb[1][1]);
                mma16(acc[mi][3], a[mi][0], a[mi][1], a[mi][2], a[mi][3], bb[1][2], bb[1][3]);
            }
        }
        __syncthreads();
    }
#undef BF_LOAD
}

// ============================================================
// Kernel 1: GroupNorm statistics
// ============================================================
__global__ void gn_stats_kernel(const float* __restrict__ x) {
    int b = blockIdx.x, g = blockIdx.y;
    const float* xp = x + ((size_t)(b * CC) + g * CPG) * NN;
    float s = 0.f, s2 = 0.f;
    for (int i = threadIdx.x; i < CPG * NN; i += 256) {
        float v = xp[i];
        s += v;
        s2 += v * v;
    }
    __shared__ float sh[256], sh2[256];
    sh[threadIdx.x] = s;
    sh2[threadIdx.x] = s2;
    __syncthreads();
    for (int off = 128; off > 0; off >>= 1) {
        if (threadIdx.x < off) {
            sh[threadIdx.x] += sh[threadIdx.x + off];
            sh2[threadIdx.x] += sh2[threadIdx.x + off];
        }
        __syncthreads();
    }
    if (threadIdx.x == 0) {
        const float inv = 1.f / (float)(CPG * NN);
        float mu = sh[0] * inv;
        float var = sh2[0] * inv - mu * mu;
        g_stats[(b * GG + g) * 2 + 0] = mu;
        g_stats[(b * GG + g) * 2 + 1] = rsqrtf(var + 1e-6f);
    }
}

// ============================================================
// Kernel 2: fold GN + softmax scale into bf16 weights + fp32 biases
// ============================================================
__global__ void fold_kernel(const float* __restrict__ qw, const float* __restrict__ qb,
                            const float* __restrict__ kw, const float* __restrict__ kb,
                            const float* __restrict__ pw,
                            const float* __restrict__ gamma, const float* __restrict__ beta) {
    int b = blockIdx.x, o0 = blockIdx.y * 128;
    __shared__ float ga[CC], be[CC];
    for (int c = threadIdx.x; c < CC; c += 256) {
        int g = c >> 4;
        float mu = g_stats[(b * GG + g) * 2 + 0];
        float rstd = g_stats[(b * GG + g) * 2 + 1];
        float gg = gamma[c] * rstd;
        ga[c] = gg;
        be[c] = beta[c] - mu * gg;
    }
    __syncthreads();
    const float s = rsqrtf((float)CC);
    for (int idx = threadIdx.x; idx < 128 * CC; idx += 256) {
        int o = o0 + (idx >> 9), c = idx & (CC - 1);
        g_qwf[((size_t)b * CC + o) * CC + c] = __float2bfloat16_rn(qw[(size_t)o * CC + c] * ga[c] * s);
        g_kwf[((size_t)b * CC + o) * CC + c] = __float2bfloat16_rn(kw[(size_t)o * CC + c] * ga[c]);
    }
    {
        int o = o0 + (threadIdx.x >> 1);
        int h = (threadIdx.x & 1) * 256;
        float sq = 0.f, sk = 0.f;
        for (int c = h; c < h + 256; c++) {
            sq += qw[(size_t)o * CC + c] * be[c];
            sk += kw[(size_t)o * CC + c] * be[c];
        }
        sq += __shfl_xor_sync(0xffffffffu, sq, 1);
        sk += __shfl_xor_sync(0xffffffffu, sk, 1);
        if ((threadIdx.x & 1) == 0) {
            g_qbf[b * CC + o] = (qb[o] + sq) * s;
            g_kbf[b * CC + o] = kb[o] + sk;
        }
    }
    if (b == 0) {
        for (int idx = threadIdx.x; idx < 128 * CC; idx += 256) {
            int o = o0 + (idx >> 9), c = idx & (CC - 1);
            g_pwf[(size_t)o * CC + c] = __float2bfloat16_rn(pw[(size_t)o * CC + c]);
        }
    }
}

// ============================================================
// Kernel 3: x[c][n] fp32 -> x_t[n][c] bf16 (tiled transpose)
// ============================================================
__global__ void xt_kernel(const float* __restrict__ x) {
    __shared__ float ts[32][33];
    int b = blockIdx.z;
    int n0 = blockIdx.x * 32, c0 = blockIdx.y * 32;
    int tx = threadIdx.x, ty = threadIdx.y;
#pragma unroll
    for (int r = 0; r < 4; r++) {
        int c = c0 + ty + r * 8;
        ts[tx][ty + r * 8] = x[((size_t)b * CC + c) * NN + n0 + tx];
    }
    __syncthreads();
#pragma unroll
    for (int r = 0; r < 4; r++) {
        int n = n0 + ty + r * 8;
        g_xt[((size_t)b * NN + n) * CC + c0 + tx] = __float2bfloat16_rn(ts[ty + r * 8][tx]);
    }
}

// ============================================================
// Kernel 4: q/k projection (bf16 GEMM) + transposed epilogues.
//   D[o 128][n 128] = W'[o][c] · x_t[n][c]^T
//   which=0 -> q_t[n][c];  which=1 -> k[c][m] AND k_t[m][c]
// ============================================================
__global__ __launch_bounds__(256, 2) void qk_bf_kernel() {
    extern __shared__ char sdyn[];
    uint32_t sbase = smem_u32(sdyn);
    int b = blockIdx.z >> 1, which = blockIdx.z & 1;
    int o_blk = blockIdx.y * 128, n_blk = blockIdx.x * 128;
    const __nv_bfloat16* A = (which ? g_kwf : g_qwf) + (size_t)b * CC * CC + (size_t)o_blk * CC;
    const __nv_bfloat16* B = g_xt + (size_t)b * NN * CC + (size_t)n_blk * CC;
    const float* bias = (which ? g_kbf : g_qbf) + b * CC;

    float acc[4][4][4] = {};
    bf_gemm(A, CC, B, CC, CC / 64, sdyn, sbase, acc);

    int tid = threadIdx.x, lane = tid & 31, wid = tid >> 5;
    int gid = lane >> 2, tig = lane & 3;
    int wm = (wid & 1) * 64, wn = (wid >> 1) * 32;

    __nv_bfloat16* T = (__nv_bfloat16*)sdyn;  // [128 n][136 o-pitch]
#pragma unroll
    for (int mi = 0; mi < 4; mi++) {
        int ol = wm + mi * 16 + gid;
        float bv0 = bias[o_blk + ol], bv1 = bias[o_blk + ol + 8];
#pragma unroll
        for (int ni = 0; ni < 4; ni++) {
            int nl = wn + ni * 8 + tig * 2;
            __nv_bfloat16 b00 = __float2bfloat16_rn(acc[mi][ni][0] + bv0);
            __nv_bfloat16 b01 = __float2bfloat16_rn(acc[mi][ni][1] + bv0);
            __nv_bfloat16 b10 = __float2bfloat16_rn(acc[mi][ni][2] + bv1);
            __nv_bfloat16 b11 = __float2bfloat16_rn(acc[mi][ni][3] + bv1);
            if (which) {
                __nv_bfloat162 p0; p0.x = b00; p0.y = b01;
                __nv_bfloat162 p1; p1.x = b10; p1.y = b11;
                *(__nv_bfloat162*)&g_kb[((size_t)b * CC + o_blk + ol) * NN + n_blk + nl] = p0;
                *(__nv_bfloat162*)&g_kb[((size_t)b * CC + o_blk + ol + 8) * NN + n_blk + nl] = p1;
            }
            T[nl * 136 + ol] = b00;
            T[(nl + 1) * 136 + ol] = b01;
            T[nl * 136 + ol + 8] = b10;
            T[(nl + 1) * 136 + ol + 8] = b11;
        }
    }
    __syncthreads();
    {
        __nv_bfloat16* dst = (which ? g_ktb : g_qt) + (size_t)b * NN * CC;
        int nl = tid >> 1, h = tid & 1;
        __nv_bfloat16* drow = dst + (size_t)(n_blk + nl) * CC + o_blk + h * 64;
        const __nv_bfloat16* srow = T + nl * 136 + h * 64;
#pragma unroll
        for (int j = 0; j < 8; j++)
            *(uint4*)(drow + j * 8) = *(const uint4*)(srow + j * 8);
    }
}

// ============================================================
// Kernel 5: scores. S[n][m] = q_t[n][c] · k_t[m][c]^T  (bf16 out)
// ============================================================
__global__ __launch_bounds__(256, 2) void scores_bf_kernel() {
    extern __shared__ char sdyn[];
    uint32_t sbase = smem_u32(sdyn);
    int b = blockIdx.z;
    int nB = blockIdx.y * 128, mB = blockIdx.x * 128;
    const __nv_bfloat16* A = g_qt + (size_t)b * NN * CC + (size_t)nB * CC;
    const __nv_bfloat16* B = g_ktb + (size_t)b * NN * CC + (size_t)mB * CC;

    float acc[4][4][4] = {};
    bf_gemm(A, CC, B, CC, CC / 64, sdyn, sbase, acc);

    int tid = threadIdx.x, lane = tid & 31, wid = tid >> 5;
    int gid = lane >> 2, tig = lane & 3;
    int wm = (wid & 1) * 64, wn = (wid >> 1) * 32;
#pragma unroll
    for (int mi = 0; mi < 4; mi++) {
        int qrow = nB + wm + mi * 16 + gid;
        __nv_bfloat16* p0 = g_s + ((size_t)b * NN + qrow) * NN + mB;
        __nv_bfloat16* p1 = p0 + (size_t)8 * NN;
#pragma unroll
        for (int ni = 0; ni < 4; ni++) {
            int cb = wn + ni * 8 + tig * 2;
            *(unsigned*)(p0 + cb) = packbf(acc[mi][ni][0], acc[mi][ni][1]);
            *(unsigned*)(p1 + cb) = packbf(acc[mi][ni][2], acc[mi][ni][3]);
        }
    }
}

// ============================================================
// Kernel 6: row softmax over m, bf16 in/out, fp32 math.
// ============================================================
__global__ void softmax_kernel() {
    int b = blockIdx.y;
    int row = blockIdx.x;
    unsigned* p = (unsigned*)(g_s + ((size_t)b * NN + row) * NN);
    int tid = threadIdx.x;

    float vals[16];
    float mx = -1e30f;
#pragma unroll
    for (int i = 0; i < 8; i++) {
        unsigned u = p[tid + i * 256];
        __nv_bfloat162 h = *reinterpret_cast<__nv_bfloat162*>(&u);
        float2 f = __bfloat1622float2(h);
        vals[2 * i] = f.x;
        vals[2 * i + 1] = f.y;
        mx = fmaxf(mx, fmaxf(f.x, f.y));
    }
    __shared__ float sred[64];
#pragma unroll
    for (int off = 16; off > 0; off >>= 1)
        mx = fmaxf(mx, __shfl_xor_sync(0xffffffffu, mx, off));
    if ((tid & 31) == 0) sred[tid >> 5] = mx;
    __syncthreads();
    if (tid < 32) {
        float v = (tid < 8) ? sred[tid] : -1e30f;
#pragma unroll
        for (int off = 4; off > 0; off >>= 1)
            v = fmaxf(v, __shfl_xor_sync(0xffffffffu, v, off));
        if (tid == 0) sred[32] = v;
    }
    __syncthreads();
    mx = sred[32];

    float sum = 0.f;
#pragma unroll
    for (int i = 0; i < 16; i++) {
        vals[i] = __expf(vals[i] - mx);
        sum += vals[i];
    }
#pragma unroll
    for (int off = 16; off > 0; off >>= 1)
        sum += __shfl_xor_sync(0xffffffffu, sum, off);
    if ((tid & 31) == 0) sred[tid >> 5] = sum;
    __syncthreads();
    if (tid < 32) {
        float v = (tid < 8) ? sred[tid] : 0.f;
#pragma unroll
        for (int off = 4; off > 0; off >>= 1)
            v += __shfl_xor_sync(0xffffffffu, v, off);
        if (tid == 0) sred[33] = v;
    }
    __syncthreads();
    float inv = 1.f / sred[33];
#pragma unroll
    for (int i = 0; i < 8; i++)
        p[tid + i * 256] = packbf(vals[2 * i] * inv, vals[2 * i + 1] * inv);
}

// ============================================================
// Kernel 7: AV. D[c 128][n 128] = k[c][m] · P[n][m]^T -> att_t[n][c] bf16
// ============================================================
__global__ __launch_bounds__(256, 2) void av_bf_kernel() {
    extern __shared__ char sdyn[];
    uint32_t sbase = smem_u32(sdyn);
    int b = blockIdx.z;
    int cB = blockIdx.y * 128, nB = blockIdx.x * 128;
    const __nv_bfloat16* A = g_kb + (size_t)b * CC * NN + (size_t)cB * NN;
    const __nv_bfloat16* B = g_s + (size_t)b * NN * NN + (size_t)nB * NN;

    float acc[4][4][4] = {};
    bf_gemm(A, NN, B, NN, NN / 64, sdyn, sbase, acc);

    int tid = threadIdx.x, lane = tid & 31, wid = tid >> 5;
    int gid = lane >> 2, tig = lane & 3;
    int wm = (wid & 1) * 64, wn = (wid >> 1) * 32;

    __nv_bfloat16* T = (__nv_bfloat16*)sdyn;  // [128 n][136 c-pitch]
#pragma unroll
    for (int mi = 0; mi < 4; mi++) {
        int cl = wm + mi * 16 + gid;
#pragma unroll
        for (int ni = 0; ni < 4; ni++) {
            int nl = wn + ni * 8 + tig * 2;
            T[nl * 136 + cl] = __float2bfloat16_rn(acc[mi][ni][0]);
            T[(nl + 1) * 136 + cl] = __float2bfloat16_rn(acc[mi][ni][1]);
            T[nl * 136 + cl + 8] = __float2bfloat16_rn(acc[mi][ni][2]);
            T[(nl + 1) * 136 + cl + 8] = __float2bfloat16_rn(acc[mi][ni][3]);
        }
    }
    __syncthreads();
    {
        int nl = tid >> 1, h = tid & 1;
        __nv_bfloat16* drow = g_attt + ((size_t)b * NN + nB + nl) * CC + cB + h * 64;
        const __nv_bfloat16* srow = T + nl * 136 + h * 64;
#pragma unroll
        for (int j = 0; j < 8; j++)
            *(uint4*)(drow + j * 8) = *(const uint4*)(srow + j * 8);
    }
}

// ============================================================
// Kernel 8: proj + bias + residual.
//   out[o][n] = x[o][n] + pb[o] + pw[o][c] · att_t[n][c]^T
// ============================================================
__global__ __launch_bounds__(256, 2) void proj_bf_kernel(const float* __restrict__ x,
                                                         const float* __restrict__ pb,
                                                         float* __restrict__ out) {
    extern __shared__ char sdyn[];
    uint32_t sbase = smem_u32(sdyn);
    int b = blockIdx.z;
    int o_blk = blockIdx.y * 128, n_blk = blockIdx.x * 128;
    const __nv_bfloat16* A = g_pwf + (size_t)o_blk * CC;
    const __nv_bfloat16* B = g_attt + (size_t)b * NN * CC + (size_t)n_blk * CC;

    float acc[4][4][4] = {};
    bf_gemm(A, CC, B, CC, CC / 64, sdyn, sbase, acc);

    int tid = threadIdx.x, lane = tid & 31, wid = tid >> 5;
    int gid = lane >> 2, tig = lane & 3;
    int wm = (wid & 1) * 64, wn = (wid >> 1) * 32;
#pragma unroll
    for (int mi = 0; mi < 4; mi++) {
        int o = o_blk + wm + mi * 16 + gid;
        float bv0 = pb[o], bv1 = pb[o + 8];
        size_t base0 = ((size_t)b * CC + o) * NN + n_blk;
        size_t base1 = base0 + (size_t)8 * NN;
#pragma unroll
        for (int ni = 0; ni < 4; ni++) {
            int cb = wn + ni * 8 + tig * 2;
            float2 x0 = *(const float2*)(x + base0 + cb);
            float2 x1 = *(const float2*)(x + base1 + cb);
            *(float2*)(out + base0 + cb) =
                make_float2(acc[mi][ni][0] + bv0 + x0.x, acc[mi][ni][1] + bv0 + x0.y);
            *(float2*)(out + base1 + cb) =
                make_float2(acc[mi][ni][2] + bv1 + x1.x, acc[mi][ni][3] + bv1 + x1.y);
        }
    }
}

// ============================================================
// launch
// ============================================================
extern "C" void kernel_launch(void* const* d_in, const int* in_sizes, int n_in,
                              void* d_out, int out_size) {
    const float* x     = (const float*)d_in[0];
    const float* gamma = (const float*)d_in[1];
    const float* beta  = (const float*)d_in[2];
    const float* q_w   = (const float*)d_in[3];
    const float* q_b   = (const float*)d_in[4];
    const float* k_w   = (const float*)d_in[5];
    const float* k_b   = (const float*)d_in[6];
    const float* p_w   = (const float*)d_in[7];
    const float* p_b   = (const float*)d_in[8];
    float* out = (float*)d_out;

    (void)in_sizes; (void)n_in; (void)out_size;

    cudaFuncSetAttribute(qk_bf_kernel, cudaFuncAttributeMaxDynamicSharedMemorySize, SMEM_DYN);
    cudaFuncSetAttribute(scores_bf_kernel, cudaFuncAttributeMaxDynamicSharedMemorySize, SMEM_DYN);
    cudaFuncSetAttribute(av_bf_kernel, cudaFuncAttributeMaxDynamicSharedMemorySize, SMEM_DYN);
    cudaFuncSetAttribute(proj_bf_kernel, cudaFuncAttributeMaxDynamicSharedMemorySize, SMEM_DYN);

    gn_stats_kernel<<<dim3(BATCH, GG), 256>>>(x);
    fold_kernel<<<dim3(BATCH, 4), 256>>>(q_w, q_b, k_w, k_b, p_w, gamma, beta);
    xt_kernel<<<dim3(NN / 32, CC / 32, BATCH), dim3(32, 8)>>>(x);

    qk_bf_kernel<<<dim3(NN / 128, CC / 128, BATCH * 2), 256, SMEM_DYN>>>();
    scores_bf_kernel<<<dim3(NN / 128, NN / 128, BATCH), 256, SMEM_DYN>>>();
    softmax_kernel<<<dim3(NN, BATCH), 256>>>();
    av_bf_kernel<<<dim3(NN / 128, CC / 128, BATCH), 256, SMEM_DYN>>>();
    proj_bf_kernel<<<dim3(NN / 128, CC / 128, BATCH), 256, SMEM_DYN>>>(x, p_b, out);
}